// round 3
// baseline (speedup 1.0000x reference)
#include <cuda_runtime.h>
#include <cstdint>

// Problem constants
constexpr int cB  = 8;
constexpr int cT  = 512;
constexpr int cD  = 1024;
constexpr int cH  = 16;
constexpr int cDK = 64;
constexpr int cS  = 2 * cT - 1;   // 1023

// ---------------------------------------------------------------------------
// Scratch (device globals — no allocation allowed)
// ---------------------------------------------------------------------------
__device__ float g_qu [cB * cH * cT * cDK];   // q + posu, [B,H,T,DK]
__device__ float g_qv [cB * cH * cT * cDK];   // q + posv
__device__ float g_k  [cB * cH * cT * cDK];   // [B,H,T,DK]
__device__ float g_v  [cB * cH * cT * cDK];   // [B,H,T,DK]
__device__ float g_p  [cH * cS * cDK];        // [H,S,DK]
__device__ float g_ctx[cB * cT * cD];         // [B,T,H,DK] flattened rows
__device__ float g_w  [cB * cH * cT * cT];    // fallback weights buffer

// ---------------------------------------------------------------------------
// Generic C = A @ B^T (+bias) with mode-specific scatter epilogues
//   MODE 0: qkv projection  -> scatter into g_qu/g_qv/g_k/g_v
//   MODE 1: pos projection  -> scatter into g_p (no bias, M=1023 guarded)
//   MODE 2: output proj     -> C[m*N+n] = c + bias[n]
// Tiling: 128x128 block, BK=16, 256 threads, 8x8 per thread.
// ---------------------------------------------------------------------------
template <int MODE>
__global__ __launch_bounds__(256)
void gemm_kernel(const float* __restrict__ A, const float* __restrict__ Bm,
                 const float* __restrict__ bias, float* __restrict__ C,
                 int M, int N, int K,
                 const float* __restrict__ pu, const float* __restrict__ pv)
{
    __shared__ float As[16][132];
    __shared__ float Bs[16][132];

    const int m0  = blockIdx.y * 128;
    const int n0  = blockIdx.x * 128;
    const int tid = threadIdx.x;
    const int tx  = tid & 15;
    const int ty  = tid >> 4;

    float acc[8][8];
#pragma unroll
    for (int i = 0; i < 8; ++i)
#pragma unroll
        for (int j = 0; j < 8; ++j) acc[i][j] = 0.f;

    for (int k0 = 0; k0 < K; k0 += 16) {
        // Stage A and B tiles (transposed in smem: [k][m])
#pragma unroll
        for (int l = 0; l < 2; ++l) {
            const int i = tid + l * 256;          // float4 index 0..511
            const int r = i >> 2;                 // tile row 0..127
            const int c = (i & 3) << 2;           // k offset 0,4,8,12
            float4 av;
            const int ar = m0 + r;
            if (MODE == 1 && ar >= M) av = make_float4(0.f, 0.f, 0.f, 0.f);
            else av = *(const float4*)(A + (size_t)ar * K + k0 + c);
            As[c + 0][r] = av.x; As[c + 1][r] = av.y;
            As[c + 2][r] = av.z; As[c + 3][r] = av.w;

            const float4 bv = *(const float4*)(Bm + (size_t)(n0 + r) * K + k0 + c);
            Bs[c + 0][r] = bv.x; Bs[c + 1][r] = bv.y;
            Bs[c + 2][r] = bv.z; Bs[c + 3][r] = bv.w;
        }
        __syncthreads();
#pragma unroll
        for (int k = 0; k < 16; ++k) {
            float a[8], b[8];
            *(float4*)(a + 0) = *(const float4*)&As[k][ty * 8];
            *(float4*)(a + 4) = *(const float4*)&As[k][ty * 8 + 4];
            *(float4*)(b + 0) = *(const float4*)&Bs[k][tx * 8];
            *(float4*)(b + 4) = *(const float4*)&Bs[k][tx * 8 + 4];
#pragma unroll
            for (int i = 0; i < 8; ++i)
#pragma unroll
                for (int j = 0; j < 8; ++j)
                    acc[i][j] = fmaf(a[i], b[j], acc[i][j]);
        }
        __syncthreads();
    }

    // Epilogue
#pragma unroll
    for (int i = 0; i < 8; ++i) {
        const int m = m0 + ty * 8 + i;
        if (MODE == 1 && m >= M) continue;
#pragma unroll
        for (int j = 0; j < 8; ++j) {
            const int n = n0 + tx * 8 + j;
            float c = acc[i][j];
            if (MODE == 0) {
                c += bias[n];
                const int part = n >> 10;
                const int nn   = n & 1023;
                const int hh   = nn >> 6, dd = nn & 63;
                const int bb   = m >> 9,  tt = m & 511;
                const size_t idx = (((size_t)bb * cH + hh) * cT + tt) * cDK + dd;
                if (part == 0) {
                    g_qu[idx] = c + pu[nn];
                    g_qv[idx] = c + pv[nn];
                } else if (part == 1) {
                    g_k[idx] = c;
                } else {
                    g_v[idx] = c;
                }
            } else if (MODE == 1) {
                const int hh = n >> 6, dd = n & 63;
                g_p[((size_t)hh * cS + m) * cDK + dd] = c;
            } else {
                C[(size_t)m * N + n] = c + bias[n];
            }
        }
    }
}

// ---------------------------------------------------------------------------
// Fused AC + BD scores with mask/scale. Block = (b, h, 32 t-rows).
// scores[t][s] = (qu[t]·k[s] + qv[t]·p[s-t+T-1]) / 8, masked -> -100000.
// Writes raw masked scores to wout; softmax_kernel normalizes in-place.
// ---------------------------------------------------------------------------
__global__ __launch_bounds__(256)
void scores_kernel(const unsigned int* __restrict__ mask, float* __restrict__ wout)
{
    __shared__ float QU[32 * 65];
    __shared__ float QV[32 * 65];
    __shared__ float Ks[32 * 65];
    __shared__ float Pw[63 * 65];

    const int blk   = blockIdx.x;
    const int ttile = blk & 15;      // T/32 = 16 tiles
    const int bh    = blk >> 4;      // 0..127
    const int h     = bh & 15;
    const int b     = bh >> 4;
    const int t0    = ttile * 32;
    const int tid   = threadIdx.x;
    const int tl    = tid >> 3;      // t row within tile 0..31
    const int sg    = tid & 7;       // s group 0..7 (4 s each)

    // Stage qu/qv rows for this t-tile
    const size_t qbase = ((size_t)bh * cT + t0) * cDK;
#pragma unroll
    for (int l = 0; l < 2; ++l) {
        const int i = tid + l * 256;
        const int r = i >> 4;
        const int c = (i & 15) << 2;
        const float4 u = *(const float4*)(g_qu + qbase + (size_t)r * cDK + c);
        QU[r * 65 + c + 0] = u.x; QU[r * 65 + c + 1] = u.y;
        QU[r * 65 + c + 2] = u.z; QU[r * 65 + c + 3] = u.w;
        const float4 v = *(const float4*)(g_qv + qbase + (size_t)r * cDK + c);
        QV[r * 65 + c + 0] = v.x; QV[r * 65 + c + 1] = v.y;
        QV[r * 65 + c + 2] = v.z; QV[r * 65 + c + 3] = v.w;
    }

    const size_t kbase = (size_t)bh * cT * cDK;
    const int    tglob = t0 + tl;
    const size_t wrow  = ((size_t)bh * cT + tglob) * cT;
    const size_t mrow  = ((size_t)b * cT + tglob) * cT;

    for (int ch = 0; ch < 16; ++ch) {
        const int s0 = ch * 32;
        __syncthreads();   // previous chunk's compute done before restaging
        // Stage k[s0..s0+31]
#pragma unroll
        for (int l = 0; l < 2; ++l) {
            const int i = tid + l * 256;
            const int r = i >> 4;
            const int c = (i & 15) << 2;
            const float4 kv = *(const float4*)(g_k + kbase + (size_t)(s0 + r) * cDK + c);
            Ks[r * 65 + c + 0] = kv.x; Ks[r * 65 + c + 1] = kv.y;
            Ks[r * 65 + c + 2] = kv.z; Ks[r * 65 + c + 3] = kv.w;
        }
        // Stage p window: global rows [s0-t0+480 .. s0-t0+480+62]  (always in [0,S))
        {
            const size_t pbase = ((size_t)h * cS + (s0 - t0 + 480)) * cDK;
            for (int i = tid; i < 63 * 16; i += 256) {
                const int r = i >> 4;
                const int c = (i & 15) << 2;
                const float4 pv = *(const float4*)(g_p + pbase + (size_t)r * cDK + c);
                Pw[r * 65 + c + 0] = pv.x; Pw[r * 65 + c + 1] = pv.y;
                Pw[r * 65 + c + 2] = pv.z; Pw[r * 65 + c + 3] = pv.w;
            }
        }
        __syncthreads();

        float a0 = 0.f, a1 = 0.f, a2 = 0.f, a3 = 0.f;
        const float* qur = QU + tl * 65;
        const float* qvr = QV + tl * 65;
        const int sb = sg * 4;
        const float* k0p = Ks + (sb + 0) * 65;
        const float* k1p = Ks + (sb + 1) * 65;
        const float* k2p = Ks + (sb + 2) * 65;
        const float* k3p = Ks + (sb + 3) * 65;
        const int pr = sb - tl + 31;              // local p row for s = sb (0..62)
        const float* p0p = Pw + (pr + 0) * 65;
        const float* p1p = Pw + (pr + 1) * 65;
        const float* p2p = Pw + (pr + 2) * 65;
        const float* p3p = Pw + (pr + 3) * 65;
#pragma unroll
        for (int k = 0; k < 64; ++k) {
            const float qu = qur[k];
            const float qv = qvr[k];
            a0 = fmaf(qu, k0p[k], fmaf(qv, p0p[k], a0));
            a1 = fmaf(qu, k1p[k], fmaf(qv, p1p[k], a1));
            a2 = fmaf(qu, k2p[k], fmaf(qv, p2p[k], a2));
            a3 = fmaf(qu, k3p[k], fmaf(qv, p3p[k], a3));
        }
        const uint4 mk = *(const uint4*)(mask + mrow + s0 + sb);
        float4 o;
        o.x = mk.x ? a0 * 0.125f : -100000.0f;
        o.y = mk.y ? a1 * 0.125f : -100000.0f;
        o.z = mk.z ? a2 * 0.125f : -100000.0f;
        o.w = mk.w ? a3 * 0.125f : -100000.0f;
        *(float4*)(wout + wrow + s0 + sb) = o;
    }
}

// ---------------------------------------------------------------------------
// In-place row softmax: block per row (512 elems), 128 threads x float4.
// ---------------------------------------------------------------------------
__global__ __launch_bounds__(128)
void softmax_kernel(float* __restrict__ w)
{
    const size_t row = blockIdx.x;
    const int tid = threadIdx.x;
    float* p = w + row * cT + tid * 4;
    const float4 v = *(const float4*)p;

    float m = fmaxf(fmaxf(v.x, v.y), fmaxf(v.z, v.w));
#pragma unroll
    for (int o = 16; o; o >>= 1) m = fmaxf(m, __shfl_xor_sync(0xffffffffu, m, o));

    __shared__ float sm[4], ss[4];
    const int wi = tid >> 5, lane = tid & 31;
    if (lane == 0) sm[wi] = m;
    __syncthreads();
    m = fmaxf(fmaxf(sm[0], sm[1]), fmaxf(sm[2], sm[3]));

    const float e0 = __expf(v.x - m);
    const float e1 = __expf(v.y - m);
    const float e2 = __expf(v.z - m);
    const float e3 = __expf(v.w - m);
    float s = e0 + e1 + e2 + e3;
#pragma unroll
    for (int o = 16; o; o >>= 1) s += __shfl_xor_sync(0xffffffffu, s, o);
    if (lane == 0) ss[wi] = s;
    __syncthreads();
    s = ss[0] + ss[1] + ss[2] + ss[3];

    const float inv = 1.0f / s;
    *(float4*)p = make_float4(e0 * inv, e1 * inv, e2 * inv, e3 * inv);
}

// ---------------------------------------------------------------------------
// ctx[b,t,h,:] = sum_s weights[b,h,t,s] * v[b,h,s,:]
// Batched GEMM: block = (bh, 64 t-rows), 64x64 tile, BK=16, 4x4 per thread.
// ---------------------------------------------------------------------------
__global__ __launch_bounds__(256)
void ctx_kernel(const float* __restrict__ w)
{
    __shared__ float Ws[16][68];
    __shared__ float Vs[16][64];

    const int bh = blockIdx.y;            // 0..127
    const int t0 = blockIdx.x * 64;
    const int b  = bh >> 4, h = bh & 15;
    const int tid = threadIdx.x;
    const int tx  = tid & 15, ty = tid >> 4;

    float acc[4][4];
#pragma unroll
    for (int i = 0; i < 4; ++i)
#pragma unroll
        for (int j = 0; j < 4; ++j) acc[i][j] = 0.f;

    const float* wrow = w + ((size_t)bh * cT + t0) * cT;
    const float* vb   = g_v + (size_t)bh * cT * cDK;
    const int rw = tid >> 2, cw = (tid & 3) << 2;     // W-tile load mapping
    const int rv = tid >> 4, cv = (tid & 15) << 2;    // V-tile load mapping

    for (int k0 = 0; k0 < cT; k0 += 16) {
        const float4 a  = *(const float4*)(wrow + (size_t)rw * cT + k0 + cw);
        const float4 vv = *(const float4*)(vb + (size_t)(k0 + rv) * cDK + cv);
        __syncthreads();
        Ws[cw + 0][rw] = a.x; Ws[cw + 1][rw] = a.y;
        Ws[cw + 2][rw] = a.z; Ws[cw + 3][rw] = a.w;
        *(float4*)&Vs[rv][cv] = vv;
        __syncthreads();
#pragma unroll
        for (int k = 0; k < 16; ++k) {
            float aa[4], bb[4];
            *(float4*)aa = *(const float4*)&Ws[k][ty * 4];
            *(float4*)bb = *(const float4*)&Vs[k][tx * 4];
#pragma unroll
            for (int i = 0; i < 4; ++i)
#pragma unroll
                for (int j = 0; j < 4; ++j)
                    acc[i][j] = fmaf(aa[i], bb[j], acc[i][j]);
        }
    }
#pragma unroll
    for (int i = 0; i < 4; ++i) {
        const int t = t0 + ty * 4 + i;
#pragma unroll
        for (int j = 0; j < 4; ++j) {
            const int d = tx * 4 + j;
            g_ctx[(((size_t)b * cT + t) * cH + h) * cDK + d] = acc[i][j];
        }
    }
}

// ---------------------------------------------------------------------------
// kernel_launch
// ---------------------------------------------------------------------------
extern "C" void kernel_launch(void* const* d_in, const int* in_sizes, int n_in,
                              void* d_out, int out_size)
{
    const float*        x    = (const float*)d_in[0];
    const unsigned int* mask = (const unsigned int*)d_in[1];   // nonzero == true
    const float*        pos  = (const float*)d_in[2];
    const float*        Wqkv = (const float*)d_in[3];
    const float*        bqkv = (const float*)d_in[4];
    const float*        Wpos = (const float*)d_in[5];
    const float*        posu = (const float*)d_in[6];
    const float*        posv = (const float*)d_in[7];
    const float*        Wout = (const float*)d_in[8];
    const float*        bout = (const float*)d_in[9];
    float* out = (float*)d_out;

    const int nOut = cB * cT * cD;          // 4,194,304
    const int nW   = cB * cH * cT * cT;     // 33,554,432

    float* wptr;
    if (out_size >= nOut + nW) {
        wptr = out + nOut;                  // weights are part of the output
    } else {
        void* p = nullptr;
        cudaGetSymbolAddress(&p, g_w);
        wptr = (float*)p;
    }
    void* pctx = nullptr;
    cudaGetSymbolAddress(&pctx, g_ctx);

    // 1. QKV projection + head split + posu/posv fold-in
    gemm_kernel<0><<<dim3(3 * cD / 128, cB * cT / 128), 256>>>(
        x, Wqkv, bqkv, nullptr, cB * cT, 3 * cD, cD, posu, posv);

    // 2. Positional projection
    gemm_kernel<1><<<dim3(cD / 128, (cS + 127) / 128), 256>>>(
        pos, Wpos, nullptr, nullptr, cS, cD, cD, nullptr, nullptr);

    // 3. Fused AC+BD scores (masked, scaled)
    scores_kernel<<<cB * cH * (cT / 32), 256>>>(mask, wptr);

    // 4. Row softmax in place -> attention weights
    softmax_kernel<<<cB * cH * cT, 128>>>(wptr);

    // 5. ctx = weights @ V
    ctx_kernel<<<dim3(cT / 64, cB * cH), 256>>>(wptr);

    // 6. out = ctx @ Wout^T + bout
    gemm_kernel<2><<<dim3(cD / 128, cB * cT / 128), 256>>>(
        (const float*)pctx, Wout, bout, out, cB * cT, cD, cD, nullptr, nullptr);
}

// round 7
// speedup vs baseline: 1.2779x; 1.2779x over previous
#include <cuda_runtime.h>
#include <cuda_bf16.h>
#include <cstdint>

// Problem constants
constexpr int cB  = 8;
constexpr int cT  = 512;
constexpr int cD  = 1024;
constexpr int cH  = 16;
constexpr int cDK = 64;
constexpr int cS  = 2 * cT - 1;   // 1023

// ---------------------------------------------------------------------------
// Scratch (device globals — no allocation allowed)
// ---------------------------------------------------------------------------
__device__ float g_qu [cB * cH * cT * cDK];   // q + posu, [B,H,T,DK]
__device__ float g_qv [cB * cH * cT * cDK];   // q + posv
__device__ float g_k  [cB * cH * cT * cDK];   // [B,H,T,DK]
__device__ float g_v  [cB * cH * cT * cDK];   // [B,H,T,DK]
__device__ float g_p  [cH * cS * cDK];        // [H,S,DK]
__device__ float g_ctx[cB * cT * cD];         // [B,T,H,DK] flattened rows
__device__ float g_w  [cB * cH * cT * cT];    // fallback weights buffer

// ---------------------------------------------------------------------------
// mma.sync m16n8k16 bf16 (sm_80 PTX path — works on compute_103 target)
// ---------------------------------------------------------------------------
__device__ __forceinline__ void mma16816(float* d, const uint32_t* a,
                                         const uint32_t* b) {
    asm volatile(
        "mma.sync.aligned.m16n8k16.row.col.f32.bf16.bf16.f32 "
        "{%0,%1,%2,%3}, {%4,%5,%6,%7}, {%8,%9}, {%0,%1,%2,%3};"
        : "+f"(d[0]), "+f"(d[1]), "+f"(d[2]), "+f"(d[3])
        : "r"(a[0]), "r"(a[1]), "r"(a[2]), "r"(a[3]), "r"(b[0]), "r"(b[1]));
}

__device__ __forceinline__ uint32_t pack_bf16(__nv_bfloat16 x, __nv_bfloat16 y) {
    __nv_bfloat162 h = __halves2bfloat162(x, y);   // x -> low halfword
    return *(uint32_t*)&h;
}

// ---------------------------------------------------------------------------
// HMMA GEMM  C = A @ B^T (+bias) with bf16 hi/lo split (fp32-grade accuracy)
//   A: [M,K] fp32 row-major, Bw: [N,K] fp32 row-major, K multiple of 32.
//   Tile 128x128 per CTA, 256 threads = 8 warps in 2(m) x 4(n); warp 64x32.
//   K-chunks of 32 (2 k16 steps). Per step: 3 partial MMAs (hh, hl, lh).
//   MODE 0: qkv scatter, MODE 1: pos scatter (M guard), MODE 2: C+bias.
// ---------------------------------------------------------------------------
template <int MODE>
__global__ __launch_bounds__(256)
void hmma_gemm(const float* __restrict__ A, const float* __restrict__ Bw,
               const float* __restrict__ bias, float* __restrict__ C,
               int M, int N, int K,
               const float* __restrict__ pu, const float* __restrict__ pv)
{
    // uint32 = packed bf16x2 along k. 16 used cols, stride 20 (conflict-free
    // for the 8-row x 4-col fragment access pattern: r*20 mod 32 spans
    // {0,20,8,28,16,4,24,12}, disjoint 4-blocks).
    __shared__ uint32_t Ah[128][20], Al[128][20], Bh[128][20], Bl[128][20];

    const int tid   = threadIdx.x;
    const int wid   = tid >> 5;
    const int lane  = tid & 31;
    const int group = lane >> 2;        // 0..7
    const int tig   = lane & 3;         // 0..3
    const int wm    = (wid & 1) * 64;   // warp m offset
    const int wn    = (wid >> 1) * 32;  // warp n offset
    const int m0    = blockIdx.y * 128;
    const int n0    = blockIdx.x * 128;

    float acc[4][4][4];
#pragma unroll
    for (int mt = 0; mt < 4; ++mt)
#pragma unroll
        for (int nt = 0; nt < 4; ++nt)
#pragma unroll
            for (int e = 0; e < 4; ++e) acc[mt][nt][e] = 0.f;

    for (int k0 = 0; k0 < K; k0 += 32) {
        __syncthreads();   // previous chunk's fragment loads complete
        // Stage + convert: 128 rows x 32 floats for A and B
#pragma unroll
        for (int l = 0; l < 4; ++l) {
            const int i  = tid + l * 256;      // 0..1023
            const int r  = i >> 3;             // 0..127
            const int c4 = (i & 7) << 2;       // 0,4,...,28
            const int c2 = c4 >> 1;            // uint32 col

            float4 av;
            if (MODE == 1 && m0 + r >= M) av = make_float4(0.f, 0.f, 0.f, 0.f);
            else av = *(const float4*)(A + (size_t)(m0 + r) * K + k0 + c4);
            {
                __nv_bfloat16 hx = __float2bfloat16_rn(av.x);
                __nv_bfloat16 hy = __float2bfloat16_rn(av.y);
                __nv_bfloat16 hz = __float2bfloat16_rn(av.z);
                __nv_bfloat16 hw = __float2bfloat16_rn(av.w);
                Ah[r][c2]     = pack_bf16(hx, hy);
                Ah[r][c2 + 1] = pack_bf16(hz, hw);
                Al[r][c2]     = pack_bf16(__float2bfloat16_rn(av.x - __bfloat162float(hx)),
                                          __float2bfloat16_rn(av.y - __bfloat162float(hy)));
                Al[r][c2 + 1] = pack_bf16(__float2bfloat16_rn(av.z - __bfloat162float(hz)),
                                          __float2bfloat16_rn(av.w - __bfloat162float(hw)));
            }
            const float4 bv = *(const float4*)(Bw + (size_t)(n0 + r) * K + k0 + c4);
            {
                __nv_bfloat16 hx = __float2bfloat16_rn(bv.x);
                __nv_bfloat16 hy = __float2bfloat16_rn(bv.y);
                __nv_bfloat16 hz = __float2bfloat16_rn(bv.z);
                __nv_bfloat16 hw = __float2bfloat16_rn(bv.w);
                Bh[r][c2]     = pack_bf16(hx, hy);
                Bh[r][c2 + 1] = pack_bf16(hz, hw);
                Bl[r][c2]     = pack_bf16(__float2bfloat16_rn(bv.x - __bfloat162float(hx)),
                                          __float2bfloat16_rn(bv.y - __bfloat162float(hy)));
                Bl[r][c2 + 1] = pack_bf16(__float2bfloat16_rn(bv.z - __bfloat162float(hz)),
                                          __float2bfloat16_rn(bv.w - __bfloat162float(hw)));
            }
        }
        __syncthreads();

#pragma unroll
        for (int ks = 0; ks < 2; ++ks) {
            const int kc = ks * 8;   // uint32 col base of this k16 step
            uint32_t afh[4][4], afl[4][4], bfh[4][2], bfl[4][2];
#pragma unroll
            for (int mt = 0; mt < 4; ++mt) {
                const int row = wm + mt * 16 + group;
                afh[mt][0] = Ah[row][kc + tig];
                afh[mt][1] = Ah[row + 8][kc + tig];
                afh[mt][2] = Ah[row][kc + tig + 4];
                afh[mt][3] = Ah[row + 8][kc + tig + 4];
                afl[mt][0] = Al[row][kc + tig];
                afl[mt][1] = Al[row + 8][kc + tig];
                afl[mt][2] = Al[row][kc + tig + 4];
                afl[mt][3] = Al[row + 8][kc + tig + 4];
            }
#pragma unroll
            for (int nt = 0; nt < 4; ++nt) {
                const int n = wn + nt * 8 + group;
                bfh[nt][0] = Bh[n][kc + tig];
                bfh[nt][1] = Bh[n][kc + tig + 4];
                bfl[nt][0] = Bl[n][kc + tig];
                bfl[nt][1] = Bl[n][kc + tig + 4];
            }
#pragma unroll
            for (int mt = 0; mt < 4; ++mt)
#pragma unroll
                for (int nt = 0; nt < 4; ++nt) {
                    mma16816(acc[mt][nt], afh[mt], bfh[nt]);
                    mma16816(acc[mt][nt], afh[mt], bfl[nt]);
                    mma16816(acc[mt][nt], afl[mt], bfh[nt]);
                }
        }
    }

    // Epilogue: per-element scatter (same math as validated SIMT version)
#pragma unroll
    for (int mt = 0; mt < 4; ++mt)
#pragma unroll
        for (int nt = 0; nt < 4; ++nt)
#pragma unroll
            for (int e = 0; e < 4; ++e) {
                const int row = wm + mt * 16 + group + ((e >> 1) << 3);
                const int col = wn + nt * 8 + tig * 2 + (e & 1);
                const int m = m0 + row;
                const int n = n0 + col;
                float val = acc[mt][nt][e];
                if (MODE == 0) {
                    val += bias[n];
                    const int part = n >> 10;
                    const int nn   = n & 1023;
                    const int hh   = nn >> 6, dd = nn & 63;
                    const int bb   = m >> 9,  tt = m & 511;
                    const size_t idx = (((size_t)bb * cH + hh) * cT + tt) * cDK + dd;
                    if (part == 0) {
                        g_qu[idx] = val + pu[nn];
                        g_qv[idx] = val + pv[nn];
                    } else if (part == 1) {
                        g_k[idx] = val;
                    } else {
                        g_v[idx] = val;
                    }
                } else if (MODE == 1) {
                    if (m < M) {
                        const int hh = n >> 6, dd = n & 63;
                        g_p[((size_t)hh * cS + m) * cDK + dd] = val;
                    }
                } else {
                    C[(size_t)m * N + n] = val + bias[n];
                }
            }
}

// ---------------------------------------------------------------------------
// Fused AC + BD scores with mask/scale. Block = (b, h, 32 t-rows).
// scores[t][s] = (qu[t]·k[s] + qv[t]·p[s-t+T-1]) / 8, masked -> -100000.
// ---------------------------------------------------------------------------
__global__ __launch_bounds__(256)
void scores_kernel(const unsigned int* __restrict__ mask, float* __restrict__ wout)
{
    __shared__ float QU[32 * 65];
    __shared__ float QV[32 * 65];
    __shared__ float Ks[32 * 65];
    __shared__ float Pw[63 * 65];

    const int blk   = blockIdx.x;
    const int ttile = blk & 15;
    const int bh    = blk >> 4;
    const int h     = bh & 15;
    const int b     = bh >> 4;
    const int t0    = ttile * 32;
    const int tid   = threadIdx.x;
    const int tl    = tid >> 3;
    const int sg    = tid & 7;

    const size_t qbase = ((size_t)bh * cT + t0) * cDK;
#pragma unroll
    for (int l = 0; l < 2; ++l) {
        const int i = tid + l * 256;
        const int r = i >> 4;
        const int c = (i & 15) << 2;
        const float4 u = *(const float4*)(g_qu + qbase + (size_t)r * cDK + c);
        QU[r * 65 + c + 0] = u.x; QU[r * 65 + c + 1] = u.y;
        QU[r * 65 + c + 2] = u.z; QU[r * 65 + c + 3] = u.w;
        const float4 v = *(const float4*)(g_qv + qbase + (size_t)r * cDK + c);
        QV[r * 65 + c + 0] = v.x; QV[r * 65 + c + 1] = v.y;
        QV[r * 65 + c + 2] = v.z; QV[r * 65 + c + 3] = v.w;
    }

    const size_t kbase = (size_t)bh * cT * cDK;
    const int    tglob = t0 + tl;
    const size_t wrow  = ((size_t)bh * cT + tglob) * cT;
    const size_t mrow  = ((size_t)b * cT + tglob) * cT;

    for (int ch = 0; ch < 16; ++ch) {
        const int s0 = ch * 32;
        __syncthreads();
#pragma unroll
        for (int l = 0; l < 2; ++l) {
            const int i = tid + l * 256;
            const int r = i >> 4;
            const int c = (i & 15) << 2;
            const float4 kv = *(const float4*)(g_k + kbase + (size_t)(s0 + r) * cDK + c);
            Ks[r * 65 + c + 0] = kv.x; Ks[r * 65 + c + 1] = kv.y;
            Ks[r * 65 + c + 2] = kv.z; Ks[r * 65 + c + 3] = kv.w;
        }
        {
            const size_t pbase = ((size_t)h * cS + (s0 - t0 + 480)) * cDK;
            for (int i = tid; i < 63 * 16; i += 256) {
                const int r = i >> 4;
                const int c = (i & 15) << 2;
                const float4 pv = *(const float4*)(g_p + pbase + (size_t)r * cDK + c);
                Pw[r * 65 + c + 0] = pv.x; Pw[r * 65 + c + 1] = pv.y;
                Pw[r * 65 + c + 2] = pv.z; Pw[r * 65 + c + 3] = pv.w;
            }
        }
        __syncthreads();

        float a0 = 0.f, a1 = 0.f, a2 = 0.f, a3 = 0.f;
        const float* qur = QU + tl * 65;
        const float* qvr = QV + tl * 65;
        const int sb = sg * 4;
        const float* k0p = Ks + (sb + 0) * 65;
        const float* k1p = Ks + (sb + 1) * 65;
        const float* k2p = Ks + (sb + 2) * 65;
        const float* k3p = Ks + (sb + 3) * 65;
        const int pr = sb - tl + 31;
        const float* p0p = Pw + (pr + 0) * 65;
        const float* p1p = Pw + (pr + 1) * 65;
        const float* p2p = Pw + (pr + 2) * 65;
        const float* p3p = Pw + (pr + 3) * 65;
#pragma unroll
        for (int k = 0; k < 64; ++k) {
            const float qu = qur[k];
            const float qv = qvr[k];
            a0 = fmaf(qu, k0p[k], fmaf(qv, p0p[k], a0));
            a1 = fmaf(qu, k1p[k], fmaf(qv, p1p[k], a1));
            a2 = fmaf(qu, k2p[k], fmaf(qv, p2p[k], a2));
            a3 = fmaf(qu, k3p[k], fmaf(qv, p3p[k], a3));
        }
        const uint4 mk = *(const uint4*)(mask + mrow + s0 + sb);
        float4 o;
        o.x = mk.x ? a0 * 0.125f : -100000.0f;
        o.y = mk.y ? a1 * 0.125f : -100000.0f;
        o.z = mk.z ? a2 * 0.125f : -100000.0f;
        o.w = mk.w ? a3 * 0.125f : -100000.0f;
        *(float4*)(wout + wrow + s0 + sb) = o;
    }
}

// ---------------------------------------------------------------------------
// In-place row softmax: block per row (512 elems), 128 threads x float4.
// ---------------------------------------------------------------------------
__global__ __launch_bounds__(128)
void softmax_kernel(float* __restrict__ w)
{
    const size_t row = blockIdx.x;
    const int tid = threadIdx.x;
    float* p = w + row * cT + tid * 4;
    const float4 v = *(const float4*)p;

    float m = fmaxf(fmaxf(v.x, v.y), fmaxf(v.z, v.w));
#pragma unroll
    for (int o = 16; o; o >>= 1) m = fmaxf(m, __shfl_xor_sync(0xffffffffu, m, o));

    __shared__ float sm[4], ss[4];
    const int wi = tid >> 5, lane = tid & 31;
    if (lane == 0) sm[wi] = m;
    __syncthreads();
    m = fmaxf(fmaxf(sm[0], sm[1]), fmaxf(sm[2], sm[3]));

    const float e0 = __expf(v.x - m);
    const float e1 = __expf(v.y - m);
    const float e2 = __expf(v.z - m);
    const float e3 = __expf(v.w - m);
    float s = e0 + e1 + e2 + e3;
#pragma unroll
    for (int o = 16; o; o >>= 1) s += __shfl_xor_sync(0xffffffffu, s, o);
    if (lane == 0) ss[wi] = s;
    __syncthreads();
    s = ss[0] + ss[1] + ss[2] + ss[3];

    const float inv = 1.0f / s;
    *(float4*)p = make_float4(e0 * inv, e1 * inv, e2 * inv, e3 * inv);
}

// ---------------------------------------------------------------------------
// ctx[b,t,h,:] = sum_s weights[b,h,t,s] * v[b,h,s,:]
// ---------------------------------------------------------------------------
__global__ __launch_bounds__(256)
void ctx_kernel(const float* __restrict__ w)
{
    __shared__ float Ws[16][68];
    __shared__ float Vs[16][64];

    const int bh = blockIdx.y;
    const int t0 = blockIdx.x * 64;
    const int b  = bh >> 4, h = bh & 15;
    const int tid = threadIdx.x;
    const int tx  = tid & 15, ty = tid >> 4;

    float acc[4][4];
#pragma unroll
    for (int i = 0; i < 4; ++i)
#pragma unroll
        for (int j = 0; j < 4; ++j) acc[i][j] = 0.f;

    const float* wrow = w + ((size_t)bh * cT + t0) * cT;
    const float* vb   = g_v + (size_t)bh * cT * cDK;
    const int rw = tid >> 2, cw = (tid & 3) << 2;
    const int rv = tid >> 4, cv = (tid & 15) << 2;

    for (int k0 = 0; k0 < cT; k0 += 16) {
        const float4 a  = *(const float4*)(wrow + (size_t)rw * cT + k0 + cw);
        const float4 vv = *(const float4*)(vb + (size_t)(k0 + rv) * cDK + cv);
        __syncthreads();
        Ws[cw + 0][rw] = a.x; Ws[cw + 1][rw] = a.y;
        Ws[cw + 2][rw] = a.z; Ws[cw + 3][rw] = a.w;
        *(float4*)&Vs[rv][cv] = vv;
        __syncthreads();
#pragma unroll
        for (int k = 0; k < 16; ++k) {
            float aa[4], bb[4];
            *(float4*)aa = *(const float4*)&Ws[k][ty * 4];
            *(float4*)bb = *(const float4*)&Vs[k][tx * 4];
#pragma unroll
            for (int i = 0; i < 4; ++i)
#pragma unroll
                for (int j = 0; j < 4; ++j)
                    acc[i][j] = fmaf(aa[i], bb[j], acc[i][j]);
        }
    }
#pragma unroll
    for (int i = 0; i < 4; ++i) {
        const int t = t0 + ty * 4 + i;
#pragma unroll
        for (int j = 0; j < 4; ++j) {
            const int d = tx * 4 + j;
            g_ctx[(((size_t)b * cT + t) * cH + h) * cDK + d] = acc[i][j];
        }
    }
}

// ---------------------------------------------------------------------------
// kernel_launch
// ---------------------------------------------------------------------------
extern "C" void kernel_launch(void* const* d_in, const int* in_sizes, int n_in,
                              void* d_out, int out_size)
{
    const float*        x    = (const float*)d_in[0];
    const unsigned int* mask = (const unsigned int*)d_in[1];
    const float*        pos  = (const float*)d_in[2];
    const float*        Wqkv = (const float*)d_in[3];
    const float*        bqkv = (const float*)d_in[4];
    const float*        Wpos = (const float*)d_in[5];
    const float*        posu = (const float*)d_in[6];
    const float*        posv = (const float*)d_in[7];
    const float*        Wout = (const float*)d_in[8];
    const float*        bout = (const float*)d_in[9];
    float* out = (float*)d_out;

    const int nOut = cB * cT * cD;
    const int nW   = cB * cH * cT * cT;

    float* wptr;
    if (out_size >= nOut + nW) {
        wptr = out + nOut;
    } else {
        void* p = nullptr;
        cudaGetSymbolAddress(&p, g_w);
        wptr = (float*)p;
    }
    void* pctx = nullptr;
    cudaGetSymbolAddress(&pctx, g_ctx);

    // 1. QKV projection + head split + posu/posv fold-in (HMMA bf16-split)
    hmma_gemm<0><<<dim3(3 * cD / 128, cB * cT / 128), 256>>>(
        x, Wqkv, bqkv, nullptr, cB * cT, 3 * cD, cD, posu, posv);

    // 2. Positional projection (HMMA, M=1023 padded)
    hmma_gemm<1><<<dim3(cD / 128, 8), 256>>>(
        pos, Wpos, nullptr, nullptr, cS, cD, cD, nullptr, nullptr);

    // 3. Fused AC+BD scores (masked, scaled)
    scores_kernel<<<cB * cH * (cT / 32), 256>>>(mask, wptr);

    // 4. Row softmax in place -> attention weights
    softmax_kernel<<<cB * cH * cT, 128>>>(wptr);

    // 5. ctx = weights @ V
    ctx_kernel<<<dim3(cT / 64, cB * cH), 256>>>(wptr);

    // 6. out = ctx @ Wout^T + bout (HMMA bf16-split)
    hmma_gemm<2><<<dim3(cD / 128, cB * cT / 128), 256>>>(
        (const float*)pctx, Wout, bout, out, cB * cT, cD, cD, nullptr, nullptr);
}

// round 8
// speedup vs baseline: 1.4490x; 1.1339x over previous
#include <cuda_runtime.h>
#include <cuda_bf16.h>
#include <cstdint>

using bf16 = __nv_bfloat16;

// Problem constants
constexpr int cB  = 8;
constexpr int cT  = 512;
constexpr int cD  = 1024;
constexpr int cH  = 16;
constexpr int cDK = 64;
constexpr int cS  = 2 * cT - 1;   // 1023
constexpr int cBH = cB * cH;      // 128

// ---------------------------------------------------------------------------
// Scratch (device globals — no allocation allowed). All bf16 pairs are exact
// hi/lo splits of fp32 values (hi = bf16(v), lo = bf16(v - hi)).
// ---------------------------------------------------------------------------
__device__ bf16  g_xh [4096 * 1024],  g_xl [4096 * 1024];    // x
__device__ bf16  g_Wqh[3072 * 1024],  g_Wql[3072 * 1024];    // Wqkv
__device__ bf16  g_Wph[1024 * 1024],  g_Wpl[1024 * 1024];    // Wpos
__device__ bf16  g_psh[1024 * 1024],  g_psl[1024 * 1024];    // pos (padded to 1024 rows)
__device__ bf16  g_Woh[1024 * 1024],  g_Wol[1024 * 1024];    // Wout
__device__ bf16  g_quh[cBH * cT * cDK], g_qul[cBH * cT * cDK];
__device__ bf16  g_qvh[cBH * cT * cDK], g_qvl[cBH * cT * cDK];
__device__ bf16  g_kh [cBH * cT * cDK], g_kl [cBH * cT * cDK];
__device__ bf16  g_vTh[cBH * cDK * cT], g_vTl[cBH * cDK * cT];   // [bh, d, t]
__device__ bf16  g_ph [cH * 1024 * cDK], g_pl [cH * 1024 * cDK]; // [h, s(pad), d]
__device__ float g_bdg[cBH * cT * cT];                           // pre-gathered BD
__device__ bf16  g_wh [cBH * cT * cT], g_wl [cBH * cT * cT];     // softmax weights
__device__ bf16  g_cth[4096 * 1024],  g_ctl[4096 * 1024];        // ctx rows
__device__ float g_w  [cBH * cT * cT];                           // fallback fp32 weights

// ---------------------------------------------------------------------------
// Helpers
// ---------------------------------------------------------------------------
__device__ __forceinline__ void mma16816(float* d, const uint32_t* a,
                                         const uint32_t* b) {
    asm volatile(
        "mma.sync.aligned.m16n8k16.row.col.f32.bf16.bf16.f32 "
        "{%0,%1,%2,%3}, {%4,%5,%6,%7}, {%8,%9}, {%0,%1,%2,%3};"
        : "+f"(d[0]), "+f"(d[1]), "+f"(d[2]), "+f"(d[3])
        : "r"(a[0]), "r"(a[1]), "r"(a[2]), "r"(a[3]), "r"(b[0]), "r"(b[1]));
}
__device__ __forceinline__ void split_store(float v, bf16* hi, bf16* lo, size_t idx) {
    bf16 h = __float2bfloat16_rn(v);
    hi[idx] = h;
    lo[idx] = __float2bfloat16_rn(v - __bfloat162float(h));
}

// ---------------------------------------------------------------------------
// fp32 -> bf16 hi/lo split converter (zero-pads [nreal, n))
// ---------------------------------------------------------------------------
__global__ __launch_bounds__(256)
void conv_split(const float* __restrict__ src, bf16* __restrict__ hi,
                bf16* __restrict__ lo, int n, int nreal)
{
    const int i0 = (blockIdx.x * 256 + threadIdx.x) * 4;
    if (i0 >= n) return;
#pragma unroll
    for (int j = 0; j < 4; ++j) {
        const int i = i0 + j;
        const float v = (i < nreal) ? src[i] : 0.f;
        split_store(v, hi, lo, i);
    }
}

// ---------------------------------------------------------------------------
// Universal HMMA GEMM  C = A @ B^T  on pre-split bf16 operands.
// Tile 128x128, 256 threads (8 warps 2m x 4n, warp 64x32), K-chunks of 32.
// 3 partial MMAs per k16 step (hh, hl, lh).
// Epilogue by MODE:
//   0 QKV  : +bqkv; scatter qu/qv (hi/lo, +posu/posv), k (hi/lo), vT (hi/lo)
//   1 POS  : scatter p hi/lo [h, s, d] (rows >= cS skipped)
//   2 BD   : pre-gathered store: s = n + m - 511; if in range -> g_bdg fp32
//   3 AC   : score = (acc + bdg)*0.125, masked -> outf fp32
//   4 CTX  : split-store ctx rows [(b*T+t)*D + h*64 + d]   (NB = 64 B-row guard)
//   5 OUT  : outf = acc + bias
// ---------------------------------------------------------------------------
template <int MODE>
__global__ __launch_bounds__(256)
void bmma(const bf16* __restrict__ Ah_, const bf16* __restrict__ Al_,
          const bf16* __restrict__ Bh_, const bf16* __restrict__ Bl_,
          const float* __restrict__ bias, const float* __restrict__ pu,
          const float* __restrict__ pv, const unsigned int* __restrict__ mask,
          float* __restrict__ outf, int K, int NB)
{
    __shared__ uint32_t sAh[128][20], sAl[128][20], sBh[128][20], sBl[128][20];

    const int tid   = threadIdx.x;
    const int wid   = tid >> 5;
    const int lane  = tid & 31;
    const int group = lane >> 2;
    const int tig   = lane & 3;
    const int wm    = (wid & 1) * 64;
    const int wn    = (wid >> 1) * 32;
    const int m0    = blockIdx.y * 128;
    const int n0    = blockIdx.x * 128;
    const int z     = blockIdx.z;

    // Batch base adjustment
    const bf16 *Ah = Ah_, *Al = Al_, *Bh = Bh_, *Bl = Bl_;
    if (MODE == 2) {            // qv @ p^T
        Ah += (size_t)z * cT * cDK;  Al += (size_t)z * cT * cDK;
        Bh += (size_t)(z & 15) * 1024 * cDK;
        Bl += (size_t)(z & 15) * 1024 * cDK;
    } else if (MODE == 3) {     // qu @ k^T
        Ah += (size_t)z * cT * cDK;  Al += (size_t)z * cT * cDK;
        Bh += (size_t)z * cT * cDK;  Bl += (size_t)z * cT * cDK;
    } else if (MODE == 4) {     // w @ vT^T
        Ah += (size_t)z * cT * cT;   Al += (size_t)z * cT * cT;
        Bh += (size_t)z * cDK * cT;  Bl += (size_t)z * cDK * cT;
    }

    float acc[4][4][4];
#pragma unroll
    for (int mt = 0; mt < 4; ++mt)
#pragma unroll
        for (int nt = 0; nt < 4; ++nt)
#pragma unroll
            for (int e = 0; e < 4; ++e) acc[mt][nt][e] = 0.f;

    const uint4 zero4 = make_uint4(0u, 0u, 0u, 0u);
    for (int k0 = 0; k0 < K; k0 += 32) {
        __syncthreads();
        // Stage: pure LDG.128 -> STS.128, no conversion
#pragma unroll
        for (int l = 0; l < 2; ++l) {
            const int i  = tid + l * 256;      // 0..511
            const int r  = i >> 2;             // row 0..127
            const int c8 = i & 3;              // 8-elem group
            const size_t ga = (size_t)(m0 + r) * K + k0 + c8 * 8;
            *(uint4*)&sAh[r][c8 * 4] = *(const uint4*)(Ah + ga);
            *(uint4*)&sAl[r][c8 * 4] = *(const uint4*)(Al + ga);
            const bool bok = (n0 + r) < NB;
            const size_t gb = (size_t)(n0 + r) * K + k0 + c8 * 8;
            *(uint4*)&sBh[r][c8 * 4] = bok ? *(const uint4*)(Bh + gb) : zero4;
            *(uint4*)&sBl[r][c8 * 4] = bok ? *(const uint4*)(Bl + gb) : zero4;
        }
        __syncthreads();

#pragma unroll
        for (int ks = 0; ks < 2; ++ks) {
            const int kc = ks * 8;
            uint32_t afh[4][4], afl[4][4], bfh[4][2], bfl[4][2];
#pragma unroll
            for (int mt = 0; mt < 4; ++mt) {
                const int row = wm + mt * 16 + group;
                afh[mt][0] = sAh[row][kc + tig];
                afh[mt][1] = sAh[row + 8][kc + tig];
                afh[mt][2] = sAh[row][kc + tig + 4];
                afh[mt][3] = sAh[row + 8][kc + tig + 4];
                afl[mt][0] = sAl[row][kc + tig];
                afl[mt][1] = sAl[row + 8][kc + tig];
                afl[mt][2] = sAl[row][kc + tig + 4];
                afl[mt][3] = sAl[row + 8][kc + tig + 4];
            }
#pragma unroll
            for (int nt = 0; nt < 4; ++nt) {
                const int n = wn + nt * 8 + group;
                bfh[nt][0] = sBh[n][kc + tig];
                bfh[nt][1] = sBh[n][kc + tig + 4];
                bfl[nt][0] = sBl[n][kc + tig];
                bfl[nt][1] = sBl[n][kc + tig + 4];
            }
#pragma unroll
            for (int mt = 0; mt < 4; ++mt)
#pragma unroll
                for (int nt = 0; nt < 4; ++nt) {
                    mma16816(acc[mt][nt], afh[mt], bfh[nt]);
                    mma16816(acc[mt][nt], afh[mt], bfl[nt]);
                    mma16816(acc[mt][nt], afl[mt], bfh[nt]);
                }
        }
    }

    // Epilogue
#pragma unroll
    for (int mt = 0; mt < 4; ++mt)
#pragma unroll
        for (int nt = 0; nt < 4; ++nt)
#pragma unroll
            for (int e = 0; e < 4; ++e) {
                const int row = wm + mt * 16 + group + ((e >> 1) << 3);
                const int col = wn + nt * 8 + tig * 2 + (e & 1);
                const int m = m0 + row;
                const int n = n0 + col;
                float val = acc[mt][nt][e];

                if (MODE == 0) {
                    val += bias[n];
                    const int part = n >> 10;
                    const int nn   = n & 1023;
                    const int hh   = nn >> 6, dd = nn & 63;
                    const int bb   = m >> 9,  tt = m & 511;
                    const int bh   = bb * cH + hh;
                    if (part == 0) {
                        const size_t idx = ((size_t)bh * cT + tt) * cDK + dd;
                        split_store(val + pu[nn], g_quh, g_qul, idx);
                        split_store(val + pv[nn], g_qvh, g_qvl, idx);
                    } else if (part == 1) {
                        const size_t idx = ((size_t)bh * cT + tt) * cDK + dd;
                        split_store(val, g_kh, g_kl, idx);
                    } else {
                        const size_t idx = ((size_t)bh * cDK + dd) * cT + tt;
                        split_store(val, g_vTh, g_vTl, idx);
                    }
                } else if (MODE == 1) {
                    if (m < cS) {
                        const int hh = n >> 6, dd = n & 63;
                        split_store(val, g_ph, g_pl,
                                    ((size_t)hh * 1024 + m) * cDK + dd);
                    }
                } else if (MODE == 2) {
                    const int s = n + m - (cT - 1);
                    if ((unsigned)s < (unsigned)cT)
                        g_bdg[((size_t)z * cT + m) * cT + s] = val;
                } else if (MODE == 3) {
                    const int bb = z >> 4;
                    const float bdv = g_bdg[((size_t)z * cT + m) * cT + n];
                    const unsigned mk = mask[((size_t)bb * cT + m) * cT + n];
                    outf[((size_t)z * cT + m) * cT + n] =
                        mk ? (val + bdv) * 0.125f : -100000.0f;
                } else if (MODE == 4) {
                    if (n < cDK) {
                        const int bb = z >> 4, hh = z & 15;
                        const size_t idx =
                            ((size_t)(bb * cT + m)) * cD + hh * cDK + n;
                        split_store(val, g_cth, g_ctl, idx);
                    }
                } else {
                    outf[(size_t)m * cD + n] = val + bias[n];
                }
            }
}

// ---------------------------------------------------------------------------
// Row softmax: fp32 in/out (wptr) + bf16 hi/lo weights for the ctx GEMM.
// ---------------------------------------------------------------------------
__global__ __launch_bounds__(128)
void softmax_kernel(float* __restrict__ w)
{
    const size_t row = blockIdx.x;
    const int tid = threadIdx.x;
    float* p = w + row * cT + tid * 4;
    const float4 v = *(const float4*)p;

    float m = fmaxf(fmaxf(v.x, v.y), fmaxf(v.z, v.w));
#pragma unroll
    for (int o = 16; o; o >>= 1) m = fmaxf(m, __shfl_xor_sync(0xffffffffu, m, o));

    __shared__ float sm[4], ss[4];
    const int wi = tid >> 5, lane = tid & 31;
    if (lane == 0) sm[wi] = m;
    __syncthreads();
    m = fmaxf(fmaxf(sm[0], sm[1]), fmaxf(sm[2], sm[3]));

    const float e0 = __expf(v.x - m);
    const float e1 = __expf(v.y - m);
    const float e2 = __expf(v.z - m);
    const float e3 = __expf(v.w - m);
    float s = e0 + e1 + e2 + e3;
#pragma unroll
    for (int o = 16; o; o >>= 1) s += __shfl_xor_sync(0xffffffffu, s, o);
    if (lane == 0) ss[wi] = s;
    __syncthreads();
    s = ss[0] + ss[1] + ss[2] + ss[3];

    const float inv = 1.0f / s;
    const float w0 = e0 * inv, w1 = e1 * inv, w2 = e2 * inv, w3 = e3 * inv;
    *(float4*)p = make_float4(w0, w1, w2, w3);

    const size_t base = row * cT + tid * 4;
    split_store(w0, g_wh, g_wl, base + 0);
    split_store(w1, g_wh, g_wl, base + 1);
    split_store(w2, g_wh, g_wl, base + 2);
    split_store(w3, g_wh, g_wl, base + 3);
}

// ---------------------------------------------------------------------------
// kernel_launch
// ---------------------------------------------------------------------------
extern "C" void kernel_launch(void* const* d_in, const int* in_sizes, int n_in,
                              void* d_out, int out_size)
{
    const float*        x    = (const float*)d_in[0];
    const unsigned int* mask = (const unsigned int*)d_in[1];
    const float*        pos  = (const float*)d_in[2];
    const float*        Wqkv = (const float*)d_in[3];
    const float*        bqkv = (const float*)d_in[4];
    const float*        Wpos = (const float*)d_in[5];
    const float*        posu = (const float*)d_in[6];
    const float*        posv = (const float*)d_in[7];
    const float*        Wout = (const float*)d_in[8];
    const float*        bout = (const float*)d_in[9];
    float* out = (float*)d_out;

    const int nOut = cB * cT * cD;
    const int nW   = cBH * cT * cT;

    float* wptr;
    if (out_size >= nOut + nW) {
        wptr = out + nOut;
    } else {
        void* p = nullptr;
        cudaGetSymbolAddress(&p, g_w);
        wptr = (float*)p;
    }

    // Device-global addresses needed host-side for kernel args
    void *pxh, *pxl, *pWqh, *pWql, *pWph, *pWpl, *ppsh, *ppsl, *pWoh, *pWol;
    void *pquh, *pqul, *pqvh, *pqvl, *pkh, *pkl, *pvTh, *pvTl, *pph, *ppl;
    void *pwh, *pwl, *pcth, *pctl;
    cudaGetSymbolAddress(&pxh, g_xh);   cudaGetSymbolAddress(&pxl, g_xl);
    cudaGetSymbolAddress(&pWqh, g_Wqh); cudaGetSymbolAddress(&pWql, g_Wql);
    cudaGetSymbolAddress(&pWph, g_Wph); cudaGetSymbolAddress(&pWpl, g_Wpl);
    cudaGetSymbolAddress(&ppsh, g_psh); cudaGetSymbolAddress(&ppsl, g_psl);
    cudaGetSymbolAddress(&pWoh, g_Woh); cudaGetSymbolAddress(&pWol, g_Wol);
    cudaGetSymbolAddress(&pquh, g_quh); cudaGetSymbolAddress(&pqul, g_qul);
    cudaGetSymbolAddress(&pqvh, g_qvh); cudaGetSymbolAddress(&pqvl, g_qvl);
    cudaGetSymbolAddress(&pkh, g_kh);   cudaGetSymbolAddress(&pkl, g_kl);
    cudaGetSymbolAddress(&pvTh, g_vTh); cudaGetSymbolAddress(&pvTl, g_vTl);
    cudaGetSymbolAddress(&pph, g_ph);   cudaGetSymbolAddress(&ppl, g_pl);
    cudaGetSymbolAddress(&pwh, g_wh);   cudaGetSymbolAddress(&pwl, g_wl);
    cudaGetSymbolAddress(&pcth, g_cth); cudaGetSymbolAddress(&pctl, g_ctl);

    // 0. One-time-per-call operand splits (pure bandwidth, ~30 MB)
    conv_split<<<4096, 256>>>(x,    (bf16*)pxh,  (bf16*)pxl,  4096 * 1024, 4096 * 1024);
    conv_split<<<3072, 256>>>(Wqkv, (bf16*)pWqh, (bf16*)pWql, 3072 * 1024, 3072 * 1024);
    conv_split<<<1024, 256>>>(Wpos, (bf16*)pWph, (bf16*)pWpl, 1024 * 1024, 1024 * 1024);
    conv_split<<<1024, 256>>>(pos,  (bf16*)ppsh, (bf16*)ppsl, 1024 * 1024, cS * 1024);
    conv_split<<<1024, 256>>>(Wout, (bf16*)pWoh, (bf16*)pWol, 1024 * 1024, 1024 * 1024);

    // 1. QKV projection (+bias, +posu/posv) -> qu/qv/k/vT bf16 splits
    bmma<0><<<dim3(24, 32), 256>>>((bf16*)pxh, (bf16*)pxl, (bf16*)pWqh, (bf16*)pWql,
                                   bqkv, posu, posv, nullptr, nullptr, 1024, 3072);

    // 2. Positional projection -> p bf16 splits
    bmma<1><<<dim3(8, 8), 256>>>((bf16*)ppsh, (bf16*)ppsl, (bf16*)pWph, (bf16*)pWpl,
                                 nullptr, nullptr, nullptr, nullptr, nullptr, 1024, 1024);

    // 3. BD = qv @ p^T, pre-gathered store
    bmma<2><<<dim3(8, 4, cBH), 256>>>((bf16*)pqvh, (bf16*)pqvl, (bf16*)pph, (bf16*)ppl,
                                      nullptr, nullptr, nullptr, nullptr, nullptr, 64, 1024);

    // 4. AC = qu @ k^T; scores = (AC + BD)*0.125 masked -> wptr
    bmma<3><<<dim3(4, 4, cBH), 256>>>((bf16*)pquh, (bf16*)pqul, (bf16*)pkh, (bf16*)pkl,
                                      nullptr, nullptr, nullptr, mask, wptr, 64, 512);

    // 5. Softmax -> fp32 weights (output) + bf16 splits for ctx
    softmax_kernel<<<cBH * cT, 128>>>(wptr);

    // 6. ctx = w @ vT^T -> ctx bf16 splits
    bmma<4><<<dim3(1, 4, cBH), 256>>>((bf16*)pwh, (bf16*)pwl, (bf16*)pvTh, (bf16*)pvTl,
                                      nullptr, nullptr, nullptr, nullptr, nullptr, 512, 64);

    // 7. out = ctx @ Wout^T + bout
    bmma<5><<<dim3(8, 32), 256>>>((bf16*)pcth, (bf16*)pctl, (bf16*)pWoh, (bf16*)pWol,
                                  bout, nullptr, nullptr, nullptr, out, 1024, 1024);
}

// round 9
// speedup vs baseline: 2.0303x; 1.4011x over previous
#include <cuda_runtime.h>
#include <cuda_bf16.h>
#include <cstdint>

using bf16 = __nv_bfloat16;

// Problem constants
constexpr int cB  = 8;
constexpr int cT  = 512;
constexpr int cD  = 1024;
constexpr int cH  = 16;
constexpr int cDK = 64;
constexpr int cS  = 2 * cT - 1;   // 1023
constexpr int cBH = cB * cH;      // 128

// ---------------------------------------------------------------------------
// Scratch (device globals — no allocation allowed). All bf16 pairs are exact
// hi/lo splits of fp32 values (hi = bf16(v), lo = bf16(v - hi)).
// ---------------------------------------------------------------------------
__device__ bf16  g_xh [4096 * 1024],  g_xl [4096 * 1024];    // x
__device__ bf16  g_Wqh[3072 * 1024],  g_Wql[3072 * 1024];    // Wqkv
__device__ bf16  g_Wph[1024 * 1024],  g_Wpl[1024 * 1024];    // Wpos
__device__ bf16  g_psh[1024 * 1024],  g_psl[1024 * 1024];    // pos (padded)
__device__ bf16  g_Woh[1024 * 1024],  g_Wol[1024 * 1024];    // Wout
__device__ bf16  g_quh[cBH * cT * cDK], g_qul[cBH * cT * cDK];
__device__ bf16  g_qvh[cBH * cT * cDK], g_qvl[cBH * cT * cDK];
__device__ bf16  g_kh [cBH * cT * cDK], g_kl [cBH * cT * cDK];
__device__ bf16  g_vTh[cBH * cDK * cT], g_vTl[cBH * cDK * cT];   // [bh, d, t]
__device__ bf16  g_ph [cH * 1024 * cDK], g_pl [cH * 1024 * cDK]; // [h, s(pad), d]
__device__ float g_bdg[cBH * cT * cT];                           // pre-gathered BD
__device__ bf16  g_wh [cBH * cT * cT], g_wl [cBH * cT * cT];     // softmax weights
__device__ bf16  g_cth[4096 * 1024],  g_ctl[4096 * 1024];        // ctx rows
__device__ float g_w  [cBH * cT * cT];                           // fallback fp32 weights

// ---------------------------------------------------------------------------
// Helpers
// ---------------------------------------------------------------------------
__device__ __forceinline__ void mma16816(float* d, const uint32_t* a,
                                         const uint32_t* b) {
    asm volatile(
        "mma.sync.aligned.m16n8k16.row.col.f32.bf16.bf16.f32 "
        "{%0,%1,%2,%3}, {%4,%5,%6,%7}, {%8,%9}, {%0,%1,%2,%3};"
        : "+f"(d[0]), "+f"(d[1]), "+f"(d[2]), "+f"(d[3])
        : "r"(a[0]), "r"(a[1]), "r"(a[2]), "r"(a[3]), "r"(b[0]), "r"(b[1]));
}
__device__ __forceinline__ void split_store(float v, bf16* hi, bf16* lo, size_t idx) {
    bf16 h = __float2bfloat16_rn(v);
    hi[idx] = h;
    lo[idx] = __float2bfloat16_rn(v - __bfloat162float(h));
}
__device__ __forceinline__ void cpasync16(uint32_t s, const void* g, uint32_t sz) {
    asm volatile("cp.async.cg.shared.global [%0], [%1], 16, %2;"
                 :: "r"(s), "l"(g), "r"(sz) : "memory");
}
#define LDM4(r, addr) \
    asm volatile("ldmatrix.sync.aligned.m8n8.x4.shared.b16 {%0,%1,%2,%3}, [%4];" \
        : "=r"((r)[0]), "=r"((r)[1]), "=r"((r)[2]), "=r"((r)[3]) : "r"(addr))

// ---------------------------------------------------------------------------
// fp32 -> bf16 hi/lo split converter (zero-pads [nreal, n))
// ---------------------------------------------------------------------------
__global__ __launch_bounds__(256)
void conv_split(const float* __restrict__ src, bf16* __restrict__ hi,
                bf16* __restrict__ lo, int n, int nreal)
{
    const int i0 = (blockIdx.x * 256 + threadIdx.x) * 4;
    if (i0 >= n) return;
#pragma unroll
    for (int j = 0; j < 4; ++j) {
        const int i = i0 + j;
        const float v = (i < nreal) ? src[i] : 0.f;
        split_store(v, hi, lo, i);
    }
}

// ---------------------------------------------------------------------------
// Universal HMMA GEMM  C = A @ B^T, pre-split bf16 operands, cp.async
// double-buffered pipeline + ldmatrix fragment loads.
// Tile 128x128, 256 threads (8 warps 2m x 4n, warp 64x32), K-chunks of 32.
// Smem layout per buffer: AH|AL|BH|BL, each 128 rows x 20 uint32 (16 used).
// Epilogue by MODE (same as validated round-8 version).
// ---------------------------------------------------------------------------
constexpr uint32_t ARR_U32 = 128 * 20;             // uint32 per array
constexpr uint32_t ARR_B   = ARR_U32 * 4;          // 10240 bytes
constexpr uint32_t BUF_B   = ARR_B * 4;            // 40960 bytes per buffer
constexpr uint32_t SMEM_B  = BUF_B * 2;            // 81920 bytes total

template <int MODE>
__global__ __launch_bounds__(256)
void bmma(const bf16* __restrict__ Ah_, const bf16* __restrict__ Al_,
          const bf16* __restrict__ Bh_, const bf16* __restrict__ Bl_,
          const float* __restrict__ bias, const float* __restrict__ pu,
          const float* __restrict__ pv, const unsigned int* __restrict__ mask,
          float* __restrict__ outf, int K, int NB)
{
    extern __shared__ uint32_t smem[];
    const uint32_t sbase = (uint32_t)__cvta_generic_to_shared(smem);

    const int tid   = threadIdx.x;
    const int wid   = tid >> 5;
    const int lane  = tid & 31;
    const int group = lane >> 2;
    const int tig   = lane & 3;
    const int wm    = (wid & 1) * 64;
    const int wn    = (wid >> 1) * 32;
    const int m0    = blockIdx.y * 128;
    const int n0    = blockIdx.x * 128;
    const int z     = blockIdx.z;

    // ldmatrix per-lane address components (quadrant mapping)
    const int lane7 = lane & 7;
    const int q     = lane >> 3;
    const int a_ro  = ((q & 1) << 3) + lane7;   // A row offset within 16-tile
    const int a_co  = (q >> 1) << 2;            // A col offset (uint32)
    const int b_ro  = ((q >> 1) << 3) + lane7;  // B row offset within 16-pair
    const int b_co  = (q & 1) << 2;             // B col offset (uint32)

    // Batch base adjustment
    const bf16 *Ah = Ah_, *Al = Al_, *Bh = Bh_, *Bl = Bl_;
    if (MODE == 2) {            // qv @ p^T
        Ah += (size_t)z * cT * cDK;  Al += (size_t)z * cT * cDK;
        Bh += (size_t)(z & 15) * 1024 * cDK;
        Bl += (size_t)(z & 15) * 1024 * cDK;
    } else if (MODE == 3) {     // qu @ k^T
        Ah += (size_t)z * cT * cDK;  Al += (size_t)z * cT * cDK;
        Bh += (size_t)z * cT * cDK;  Bl += (size_t)z * cT * cDK;
    } else if (MODE == 4) {     // w @ vT^T
        Ah += (size_t)z * cT * cT;   Al += (size_t)z * cT * cT;
        Bh += (size_t)z * cDK * cT;  Bl += (size_t)z * cDK * cT;
    }

    float acc[4][4][4];
#pragma unroll
    for (int mt = 0; mt < 4; ++mt)
#pragma unroll
        for (int nt = 0; nt < 4; ++nt)
#pragma unroll
            for (int e = 0; e < 4; ++e) acc[mt][nt][e] = 0.f;

    const int nIter = K / 32;

    // ---- staging via cp.async -------------------------------------------
    auto stage = [&](int it) {
        const int k0 = it * 32;
        const uint32_t bufo = (uint32_t)(it & 1) * BUF_B;
#pragma unroll
        for (int l = 0; l < 2; ++l) {
            const int i  = tid + l * 256;      // 0..511
            const int r  = i >> 2;             // row 0..127
            const int c8 = i & 3;              // 8-elem (16B) group
            const uint32_t so = bufo + (uint32_t)(r * 80 + c8 * 16);
            const size_t ga = (size_t)(m0 + r) * K + k0 + c8 * 8;
            cpasync16(sbase + so,             Ah + ga, 16);
            cpasync16(sbase + ARR_B + so,     Al + ga, 16);
            const bool bok = (n0 + r) < NB;
            const int  rb  = bok ? (n0 + r) : 0;
            const uint32_t sz = bok ? 16u : 0u;
            const size_t gb = (size_t)rb * K + k0 + c8 * 8;
            cpasync16(sbase + 2 * ARR_B + so, Bh + gb, sz);
            cpasync16(sbase + 3 * ARR_B + so, Bl + gb, sz);
        }
        asm volatile("cp.async.commit_group;" ::: "memory");
    };

    stage(0);
    for (int it = 0; it < nIter; ++it) {
        __syncthreads();                       // all warps done with buf (it+1)&1
        if (it + 1 < nIter) {
            stage(it + 1);
            asm volatile("cp.async.wait_group 1;" ::: "memory");
        } else {
            asm volatile("cp.async.wait_group 0;" ::: "memory");
        }
        __syncthreads();                       // chunk it visible

        const uint32_t bo = sbase + (uint32_t)(it & 1) * BUF_B;
#pragma unroll
        for (int ks = 0; ks < 2; ++ks) {
            const int kc = ks * 8;
            uint32_t afh[4][4], afl[4][4], bfh[4][2], bfl[4][2];
#pragma unroll
            for (int mt = 0; mt < 4; ++mt) {
                const uint32_t ra = bo +
                    (uint32_t)((wm + mt * 16 + a_ro) * 80 + (kc + a_co) * 4);
                LDM4(afh[mt], ra);
                LDM4(afl[mt], ra + ARR_B);
            }
#pragma unroll
            for (int np = 0; np < 2; ++np) {
                const uint32_t rb = bo + 2 * ARR_B +
                    (uint32_t)((wn + np * 16 + b_ro) * 80 + (kc + b_co) * 4);
                uint32_t t[4];
                LDM4(t, rb);
                bfh[np * 2][0] = t[0]; bfh[np * 2][1] = t[1];
                bfh[np * 2 + 1][0] = t[2]; bfh[np * 2 + 1][1] = t[3];
                LDM4(t, rb + ARR_B);
                bfl[np * 2][0] = t[0]; bfl[np * 2][1] = t[1];
                bfl[np * 2 + 1][0] = t[2]; bfl[np * 2 + 1][1] = t[3];
            }
#pragma unroll
            for (int mt = 0; mt < 4; ++mt)
#pragma unroll
                for (int nt = 0; nt < 4; ++nt) {
                    mma16816(acc[mt][nt], afh[mt], bfh[nt]);
                    mma16816(acc[mt][nt], afh[mt], bfl[nt]);
                    mma16816(acc[mt][nt], afl[mt], bfh[nt]);
                }
        }
    }

    // Epilogue (identical to validated round-8 version)
#pragma unroll
    for (int mt = 0; mt < 4; ++mt)
#pragma unroll
        for (int nt = 0; nt < 4; ++nt)
#pragma unroll
            for (int e = 0; e < 4; ++e) {
                const int row = wm + mt * 16 + group + ((e >> 1) << 3);
                const int col = wn + nt * 8 + tig * 2 + (e & 1);
                const int m = m0 + row;
                const int n = n0 + col;
                float val = acc[mt][nt][e];

                if (MODE == 0) {
                    val += bias[n];
                    const int part = n >> 10;
                    const int nn   = n & 1023;
                    const int hh   = nn >> 6, dd = nn & 63;
                    const int bb   = m >> 9,  tt = m & 511;
                    const int bh   = bb * cH + hh;
                    if (part == 0) {
                        const size_t idx = ((size_t)bh * cT + tt) * cDK + dd;
                        split_store(val + pu[nn], g_quh, g_qul, idx);
                        split_store(val + pv[nn], g_qvh, g_qvl, idx);
                    } else if (part == 1) {
                        const size_t idx = ((size_t)bh * cT + tt) * cDK + dd;
                        split_store(val, g_kh, g_kl, idx);
                    } else {
                        const size_t idx = ((size_t)bh * cDK + dd) * cT + tt;
                        split_store(val, g_vTh, g_vTl, idx);
                    }
                } else if (MODE == 1) {
                    if (m < cS) {
                        const int hh = n >> 6, dd = n & 63;
                        split_store(val, g_ph, g_pl,
                                    ((size_t)hh * 1024 + m) * cDK + dd);
                    }
                } else if (MODE == 2) {
                    const int s = n + m - (cT - 1);
                    if ((unsigned)s < (unsigned)cT)
                        g_bdg[((size_t)z * cT + m) * cT + s] = val;
                } else if (MODE == 3) {
                    const int bb = z >> 4;
                    const float bdv = g_bdg[((size_t)z * cT + m) * cT + n];
                    const unsigned mk = mask[((size_t)bb * cT + m) * cT + n];
                    outf[((size_t)z * cT + m) * cT + n] =
                        mk ? (val + bdv) * 0.125f : -100000.0f;
                } else if (MODE == 4) {
                    if (n < cDK) {
                        const int bb = z >> 4, hh = z & 15;
                        const size_t idx =
                            ((size_t)(bb * cT + m)) * cD + hh * cDK + n;
                        split_store(val, g_cth, g_ctl, idx);
                    }
                } else {
                    outf[(size_t)m * cD + n] = val + bias[n];
                }
            }
}

// ---------------------------------------------------------------------------
// Row softmax: fp32 in/out (wptr) + bf16 hi/lo weights for the ctx GEMM.
// ---------------------------------------------------------------------------
__global__ __launch_bounds__(128)
void softmax_kernel(float* __restrict__ w)
{
    const size_t row = blockIdx.x;
    const int tid = threadIdx.x;
    float* p = w + row * cT + tid * 4;
    const float4 v = *(const float4*)p;

    float m = fmaxf(fmaxf(v.x, v.y), fmaxf(v.z, v.w));
#pragma unroll
    for (int o = 16; o; o >>= 1) m = fmaxf(m, __shfl_xor_sync(0xffffffffu, m, o));

    __shared__ float sm[4], ss[4];
    const int wi = tid >> 5, lane = tid & 31;
    if (lane == 0) sm[wi] = m;
    __syncthreads();
    m = fmaxf(fmaxf(sm[0], sm[1]), fmaxf(sm[2], sm[3]));

    const float e0 = __expf(v.x - m);
    const float e1 = __expf(v.y - m);
    const float e2 = __expf(v.z - m);
    const float e3 = __expf(v.w - m);
    float s = e0 + e1 + e2 + e3;
#pragma unroll
    for (int o = 16; o; o >>= 1) s += __shfl_xor_sync(0xffffffffu, s, o);
    if (lane == 0) ss[wi] = s;
    __syncthreads();
    s = ss[0] + ss[1] + ss[2] + ss[3];

    const float inv = 1.0f / s;
    const float w0 = e0 * inv, w1 = e1 * inv, w2 = e2 * inv, w3 = e3 * inv;
    *(float4*)p = make_float4(w0, w1, w2, w3);

    const size_t base = row * cT + tid * 4;
    split_store(w0, g_wh, g_wl, base + 0);
    split_store(w1, g_wh, g_wl, base + 1);
    split_store(w2, g_wh, g_wl, base + 2);
    split_store(w3, g_wh, g_wl, base + 3);
}

// ---------------------------------------------------------------------------
// kernel_launch
// ---------------------------------------------------------------------------
extern "C" void kernel_launch(void* const* d_in, const int* in_sizes, int n_in,
                              void* d_out, int out_size)
{
    const float*        x    = (const float*)d_in[0];
    const unsigned int* mask = (const unsigned int*)d_in[1];
    const float*        pos  = (const float*)d_in[2];
    const float*        Wqkv = (const float*)d_in[3];
    const float*        bqkv = (const float*)d_in[4];
    const float*        Wpos = (const float*)d_in[5];
    const float*        posu = (const float*)d_in[6];
    const float*        posv = (const float*)d_in[7];
    const float*        Wout = (const float*)d_in[8];
    const float*        bout = (const float*)d_in[9];
    float* out = (float*)d_out;

    const int nOut = cB * cT * cD;
    const int nW   = cBH * cT * cT;

    float* wptr;
    if (out_size >= nOut + nW) {
        wptr = out + nOut;
    } else {
        void* p = nullptr;
        cudaGetSymbolAddress(&p, g_w);
        wptr = (float*)p;
    }

    void *pxh, *pxl, *pWqh, *pWql, *pWph, *pWpl, *ppsh, *ppsl, *pWoh, *pWol;
    void *pquh, *pqul, *pqvh, *pqvl, *pkh, *pkl, *pvTh, *pvTl, *pph, *ppl;
    void *pwh, *pwl, *pcth, *pctl;
    cudaGetSymbolAddress(&pxh, g_xh);   cudaGetSymbolAddress(&pxl, g_xl);
    cudaGetSymbolAddress(&pWqh, g_Wqh); cudaGetSymbolAddress(&pWql, g_Wql);
    cudaGetSymbolAddress(&pWph, g_Wph); cudaGetSymbolAddress(&pWpl, g_Wpl);
    cudaGetSymbolAddress(&ppsh, g_psh); cudaGetSymbolAddress(&ppsl, g_psl);
    cudaGetSymbolAddress(&pWoh, g_Woh); cudaGetSymbolAddress(&pWol, g_Wol);
    cudaGetSymbolAddress(&pquh, g_quh); cudaGetSymbolAddress(&pqul, g_qul);
    cudaGetSymbolAddress(&pqvh, g_qvh); cudaGetSymbolAddress(&pqvl, g_qvl);
    cudaGetSymbolAddress(&pkh, g_kh);   cudaGetSymbolAddress(&pkl, g_kl);
    cudaGetSymbolAddress(&pvTh, g_vTh); cudaGetSymbolAddress(&pvTl, g_vTl);
    cudaGetSymbolAddress(&pph, g_ph);   cudaGetSymbolAddress(&ppl, g_pl);
    cudaGetSymbolAddress(&pwh, g_wh);   cudaGetSymbolAddress(&pwl, g_wl);
    cudaGetSymbolAddress(&pcth, g_cth); cudaGetSymbolAddress(&pctl, g_ctl);

    cudaFuncSetAttribute(bmma<0>, cudaFuncAttributeMaxDynamicSharedMemorySize, SMEM_B);
    cudaFuncSetAttribute(bmma<1>, cudaFuncAttributeMaxDynamicSharedMemorySize, SMEM_B);
    cudaFuncSetAttribute(bmma<2>, cudaFuncAttributeMaxDynamicSharedMemorySize, SMEM_B);
    cudaFuncSetAttribute(bmma<3>, cudaFuncAttributeMaxDynamicSharedMemorySize, SMEM_B);
    cudaFuncSetAttribute(bmma<4>, cudaFuncAttributeMaxDynamicSharedMemorySize, SMEM_B);
    cudaFuncSetAttribute(bmma<5>, cudaFuncAttributeMaxDynamicSharedMemorySize, SMEM_B);

    // 0. One-time-per-call operand splits (pure bandwidth, ~30 MB)
    conv_split<<<4096, 256>>>(x,    (bf16*)pxh,  (bf16*)pxl,  4096 * 1024, 4096 * 1024);
    conv_split<<<3072, 256>>>(Wqkv, (bf16*)pWqh, (bf16*)pWql, 3072 * 1024, 3072 * 1024);
    conv_split<<<1024, 256>>>(Wpos, (bf16*)pWph, (bf16*)pWpl, 1024 * 1024, 1024 * 1024);
    conv_split<<<1024, 256>>>(pos,  (bf16*)ppsh, (bf16*)ppsl, 1024 * 1024, cS * 1024);
    conv_split<<<1024, 256>>>(Wout, (bf16*)pWoh, (bf16*)pWol, 1024 * 1024, 1024 * 1024);

    // 1. QKV projection (+bias, +posu/posv) -> qu/qv/k/vT bf16 splits
    bmma<0><<<dim3(24, 32), 256, SMEM_B>>>((bf16*)pxh, (bf16*)pxl, (bf16*)pWqh, (bf16*)pWql,
                                           bqkv, posu, posv, nullptr, nullptr, 1024, 3072);

    // 2. Positional projection -> p bf16 splits
    bmma<1><<<dim3(8, 8), 256, SMEM_B>>>((bf16*)ppsh, (bf16*)ppsl, (bf16*)pWph, (bf16*)pWpl,
                                         nullptr, nullptr, nullptr, nullptr, nullptr, 1024, 1024);

    // 3. BD = qv @ p^T, pre-gathered store
    bmma<2><<<dim3(8, 4, cBH), 256, SMEM_B>>>((bf16*)pqvh, (bf16*)pqvl, (bf16*)pph, (bf16*)ppl,
                                              nullptr, nullptr, nullptr, nullptr, nullptr, 64, 1024);

    // 4. AC = qu @ k^T; scores = (AC + BD)*0.125 masked -> wptr
    bmma<3><<<dim3(4, 4, cBH), 256, SMEM_B>>>((bf16*)pquh, (bf16*)pqul, (bf16*)pkh, (bf16*)pkl,
                                              nullptr, nullptr, nullptr, mask, wptr, 64, 512);

    // 5. Softmax -> fp32 weights (output) + bf16 splits for ctx
    softmax_kernel<<<cBH * cT, 128>>>(wptr);

    // 6. ctx = w @ vT^T -> ctx bf16 splits
    bmma<4><<<dim3(1, 4, cBH), 256, SMEM_B>>>((bf16*)pwh, (bf16*)pwl, (bf16*)pvTh, (bf16*)pvTl,
                                              nullptr, nullptr, nullptr, nullptr, nullptr, 512, 64);

    // 7. out = ctx @ Wout^T + bout
    bmma<5><<<dim3(8, 32), 256, SMEM_B>>>((bf16*)pcth, (bf16*)pctl, (bf16*)pWoh, (bf16*)pWol,
                                          bout, nullptr, nullptr, nullptr, out, 1024, 1024);
}

// round 10
// speedup vs baseline: 2.5754x; 1.2685x over previous
#include <cuda_runtime.h>
#include <cuda_bf16.h>
#include <cstdint>

using bf16 = __nv_bfloat16;

// Problem constants
constexpr int cB  = 8;
constexpr int cT  = 512;
constexpr int cD  = 1024;
constexpr int cH  = 16;
constexpr int cDK = 64;
constexpr int cS  = 2 * cT - 1;   // 1023
constexpr int cBH = cB * cH;      // 128

// ---------------------------------------------------------------------------
// Scratch (device globals — no allocation allowed). All bf16 pairs are exact
// hi/lo splits of fp32 values (hi = bf16(v), lo = bf16(v - hi)).
// ---------------------------------------------------------------------------
__device__ bf16  g_xh [4096 * 1024],  g_xl [4096 * 1024];    // x
__device__ bf16  g_Wqh[3072 * 1024],  g_Wql[3072 * 1024];    // Wqkv
__device__ bf16  g_Wph[1024 * 1024],  g_Wpl[1024 * 1024];    // Wpos
__device__ bf16  g_psh[1024 * 1024],  g_psl[1024 * 1024];    // pos (padded)
__device__ bf16  g_Woh[1024 * 1024],  g_Wol[1024 * 1024];    // Wout
__device__ bf16  g_quh[cBH * cT * cDK], g_qul[cBH * cT * cDK];
__device__ bf16  g_qvh[cBH * cT * cDK], g_qvl[cBH * cT * cDK];
__device__ bf16  g_kh [cBH * cT * cDK], g_kl [cBH * cT * cDK];
__device__ bf16  g_vTh[cBH * cDK * cT], g_vTl[cBH * cDK * cT];   // [bh, d, t]
__device__ bf16  g_ph [cH * 1024 * cDK], g_pl [cH * 1024 * cDK]; // [h, s(pad), d]
__device__ float g_bdg[cBH * cT * cT];                           // pre-gathered BD
__device__ bf16  g_wh [cBH * cT * cT], g_wl [cBH * cT * cT];     // softmax weights
__device__ bf16  g_cth[4096 * 1024],  g_ctl[4096 * 1024];        // ctx rows
__device__ float g_w  [cBH * cT * cT];                           // fallback fp32 weights

// ---------------------------------------------------------------------------
// Helpers
// ---------------------------------------------------------------------------
__device__ __forceinline__ void mma16816(float* d, const uint32_t* a,
                                         const uint32_t* b) {
    asm volatile(
        "mma.sync.aligned.m16n8k16.row.col.f32.bf16.bf16.f32 "
        "{%0,%1,%2,%3}, {%4,%5,%6,%7}, {%8,%9}, {%0,%1,%2,%3};"
        : "+f"(d[0]), "+f"(d[1]), "+f"(d[2]), "+f"(d[3])
        : "r"(a[0]), "r"(a[1]), "r"(a[2]), "r"(a[3]), "r"(b[0]), "r"(b[1]));
}
__device__ __forceinline__ void split_store(float v, bf16* hi, bf16* lo, size_t idx) {
    bf16 h = __float2bfloat16_rn(v);
    hi[idx] = h;
    lo[idx] = __float2bfloat16_rn(v - __bfloat162float(h));
}
// Paired split store: idx must be 2-element aligned, v0 -> idx, v1 -> idx+1.
__device__ __forceinline__ void split_store2(float v0, float v1,
                                             bf16* hi, bf16* lo, size_t idx) {
    bf16 h0 = __float2bfloat16_rn(v0);
    bf16 h1 = __float2bfloat16_rn(v1);
    __nv_bfloat162 hh = __halves2bfloat162(h0, h1);
    *(__nv_bfloat162*)(hi + idx) = hh;
    __nv_bfloat162 ll = __halves2bfloat162(
        __float2bfloat16_rn(v0 - __bfloat162float(h0)),
        __float2bfloat16_rn(v1 - __bfloat162float(h1)));
    *(__nv_bfloat162*)(lo + idx) = ll;
}
__device__ __forceinline__ uint32_t pk2(bf16 a, bf16 b) {
    __nv_bfloat162 t = __halves2bfloat162(a, b);
    return *(uint32_t*)&t;
}
__device__ __forceinline__ void cpasync16(uint32_t s, const void* g, uint32_t sz) {
    asm volatile("cp.async.cg.shared.global [%0], [%1], 16, %2;"
                 :: "r"(s), "l"(g), "r"(sz) : "memory");
}
#define LDM4(r, addr) \
    asm volatile("ldmatrix.sync.aligned.m8n8.x4.shared.b16 {%0,%1,%2,%3}, [%4];" \
        : "=r"((r)[0]), "=r"((r)[1]), "=r"((r)[2]), "=r"((r)[3]) : "r"(addr))

// ---------------------------------------------------------------------------
// fp32 -> bf16 hi/lo split converter (zero-pads [nreal, n)), vector stores
// ---------------------------------------------------------------------------
__global__ __launch_bounds__(256)
void conv_split(const float* __restrict__ src, bf16* __restrict__ hi,
                bf16* __restrict__ lo, int n, int nreal)
{
    const int i0 = (blockIdx.x * 256 + threadIdx.x) * 4;
    if (i0 >= n) return;
    float v[4];
#pragma unroll
    for (int j = 0; j < 4; ++j) {
        const int i = i0 + j;
        v[j] = (i < nreal) ? src[i] : 0.f;
    }
    bf16 h[4], l[4];
#pragma unroll
    for (int j = 0; j < 4; ++j) {
        h[j] = __float2bfloat16_rn(v[j]);
        l[j] = __float2bfloat16_rn(v[j] - __bfloat162float(h[j]));
    }
    *(uint2*)(hi + i0) = make_uint2(pk2(h[0], h[1]), pk2(h[2], h[3]));
    *(uint2*)(lo + i0) = make_uint2(pk2(l[0], l[1]), pk2(l[2], l[3]));
}

// ---------------------------------------------------------------------------
// Universal HMMA GEMM  C = A @ B^T, pre-split bf16 operands, cp.async
// double-buffered pipeline + ldmatrix fragment loads.
// Tile 128 x TN (TN = 128 or 64), 256 threads (8 warps 2m x 4n), K-chunks 32.
// Epilogue by MODE:
//   0 QKV : +bqkv; scatter qu/qv (+posu/posv), k, vT  (hi/lo splits)
//   1 POS : scatter p hi/lo [h, s, d] (rows >= cS skipped)
//   2 BD  : pre-gathered store s = n + m - 511 (window-skipped grid)
//   3 AC  : score = (acc + bdg)*0.125, masked -> outf fp32
//   4 CTX : split-store ctx rows (TN = 64)
//   5 OUT : outf = acc + bias
// ---------------------------------------------------------------------------
constexpr uint32_t ARR_U32 = 128 * 20;             // uint32 per array
constexpr uint32_t ARR_B   = ARR_U32 * 4;          // 10240 bytes
constexpr uint32_t BUF_B   = ARR_B * 4;            // 40960 bytes per buffer
constexpr uint32_t SMEM_B  = BUF_B * 2;            // 81920 bytes total

template <int MODE, int TN = 128>
__global__ __launch_bounds__(256)
void bmma(const bf16* __restrict__ Ah_, const bf16* __restrict__ Al_,
          const bf16* __restrict__ Bh_, const bf16* __restrict__ Bl_,
          const float* __restrict__ bias, const float* __restrict__ pu,
          const float* __restrict__ pv, const unsigned int* __restrict__ mask,
          float* __restrict__ outf, int K, int NB)
{
    constexpr int NTT = TN / 32;       // n-frag count per warp (4 or 2)
    constexpr int NP  = TN / 64;       // 16-row ldmatrix pair count (2 or 1)

    extern __shared__ uint32_t smem[];
    const uint32_t sbase = (uint32_t)__cvta_generic_to_shared(smem);

    const int tid   = threadIdx.x;
    const int wid   = tid >> 5;
    const int lane  = tid & 31;
    const int group = lane >> 2;
    const int tig   = lane & 3;
    const int wm    = (wid & 1) * 64;
    const int wn    = (wid >> 1) * (TN / 4);
    const int m0    = blockIdx.y * 128;
    // BD window remap: only n-tiles (3 - by + bx), bx in [0,5), cover the
    // gathered band s = n + m - 511 in [0, 512).
    const int n0    = (MODE == 2) ? (3 - (int)blockIdx.y + (int)blockIdx.x) * 128
                                  : blockIdx.x * TN;
    const int z     = blockIdx.z;

    // ldmatrix per-lane address components (quadrant mapping)
    const int lane7 = lane & 7;
    const int q     = lane >> 3;
    const int a_ro  = ((q & 1) << 3) + lane7;
    const int a_co  = (q >> 1) << 2;
    const int b_ro  = ((q >> 1) << 3) + lane7;
    const int b_co  = (q & 1) << 2;

    // Batch base adjustment
    const bf16 *Ah = Ah_, *Al = Al_, *Bh = Bh_, *Bl = Bl_;
    if (MODE == 2) {            // qv @ p^T
        Ah += (size_t)z * cT * cDK;  Al += (size_t)z * cT * cDK;
        Bh += (size_t)(z & 15) * 1024 * cDK;
        Bl += (size_t)(z & 15) * 1024 * cDK;
    } else if (MODE == 3) {     // qu @ k^T
        Ah += (size_t)z * cT * cDK;  Al += (size_t)z * cT * cDK;
        Bh += (size_t)z * cT * cDK;  Bl += (size_t)z * cT * cDK;
    } else if (MODE == 4) {     // w @ vT^T
        Ah += (size_t)z * cT * cT;   Al += (size_t)z * cT * cT;
        Bh += (size_t)z * cDK * cT;  Bl += (size_t)z * cDK * cT;
    }

    float acc[4][NTT][4];
#pragma unroll
    for (int mt = 0; mt < 4; ++mt)
#pragma unroll
        for (int nt = 0; nt < NTT; ++nt)
#pragma unroll
            for (int e = 0; e < 4; ++e) acc[mt][nt][e] = 0.f;

    const int nIter = K / 32;

    auto stage = [&](int it) {
        const int k0 = it * 32;
        const uint32_t bufo = (uint32_t)(it & 1) * BUF_B;
#pragma unroll
        for (int l = 0; l < 2; ++l) {
            const int i  = tid + l * 256;
            const int r  = i >> 2;
            const int c8 = i & 3;
            const uint32_t so = bufo + (uint32_t)(r * 80 + c8 * 16);
            const size_t ga = (size_t)(m0 + r) * K + k0 + c8 * 8;
            cpasync16(sbase + so,             Ah + ga, 16);
            cpasync16(sbase + ARR_B + so,     Al + ga, 16);
            if (r < TN) {
                const bool bok = (n0 + r) < NB;
                const int  rb  = bok ? (n0 + r) : 0;
                const uint32_t sz = bok ? 16u : 0u;
                const size_t gb = (size_t)rb * K + k0 + c8 * 8;
                cpasync16(sbase + 2 * ARR_B + so, Bh + gb, sz);
                cpasync16(sbase + 3 * ARR_B + so, Bl + gb, sz);
            }
        }
        asm volatile("cp.async.commit_group;" ::: "memory");
    };

    stage(0);
    for (int it = 0; it < nIter; ++it) {
        __syncthreads();
        if (it + 1 < nIter) {
            stage(it + 1);
            asm volatile("cp.async.wait_group 1;" ::: "memory");
        } else {
            asm volatile("cp.async.wait_group 0;" ::: "memory");
        }
        __syncthreads();

        const uint32_t bo = sbase + (uint32_t)(it & 1) * BUF_B;
#pragma unroll
        for (int ks = 0; ks < 2; ++ks) {
            const int kc = ks * 8;
            uint32_t afh[4][4], afl[4][4], bfh[NTT][2], bfl[NTT][2];
#pragma unroll
            for (int mt = 0; mt < 4; ++mt) {
                const uint32_t ra = bo +
                    (uint32_t)((wm + mt * 16 + a_ro) * 80 + (kc + a_co) * 4);
                LDM4(afh[mt], ra);
                LDM4(afl[mt], ra + ARR_B);
            }
#pragma unroll
            for (int np = 0; np < NP; ++np) {
                const uint32_t rb = bo + 2 * ARR_B +
                    (uint32_t)((wn + np * 16 + b_ro) * 80 + (kc + b_co) * 4);
                uint32_t t[4];
                LDM4(t, rb);
                bfh[np * 2][0] = t[0]; bfh[np * 2][1] = t[1];
                bfh[np * 2 + 1][0] = t[2]; bfh[np * 2 + 1][1] = t[3];
                LDM4(t, rb + ARR_B);
                bfl[np * 2][0] = t[0]; bfl[np * 2][1] = t[1];
                bfl[np * 2 + 1][0] = t[2]; bfl[np * 2 + 1][1] = t[3];
            }
#pragma unroll
            for (int mt = 0; mt < 4; ++mt)
#pragma unroll
                for (int nt = 0; nt < NTT; ++nt) {
                    mma16816(acc[mt][nt], afh[mt], bfh[nt]);
                    mma16816(acc[mt][nt], afh[mt], bfl[nt]);
                    mma16816(acc[mt][nt], afl[mt], bfh[nt]);
                }
        }
    }

    // Epilogue: element pairs (e, e+1) are same-row adjacent columns.
#pragma unroll
    for (int mt = 0; mt < 4; ++mt)
#pragma unroll
        for (int nt = 0; nt < NTT; ++nt)
#pragma unroll
            for (int ep = 0; ep < 2; ++ep) {
                const int row = wm + mt * 16 + group + ep * 8;
                const int col = wn + nt * 8 + tig * 2;
                const int m = m0 + row;
                const int n = n0 + col;           // even
                float v0 = acc[mt][nt][ep * 2];
                float v1 = acc[mt][nt][ep * 2 + 1];

                if (MODE == 0) {
                    v0 += bias[n];  v1 += bias[n + 1];
                    const int part = n >> 10;
                    const int nn   = n & 1023;    // even; pair stays in part
                    const int hh   = nn >> 6, dd = nn & 63;
                    const int bb   = m >> 9,  tt = m & 511;
                    const int bh   = bb * cH + hh;
                    if (part == 0) {
                        const size_t idx = ((size_t)bh * cT + tt) * cDK + dd;
                        split_store2(v0 + pu[nn], v1 + pu[nn + 1], g_quh, g_qul, idx);
                        split_store2(v0 + pv[nn], v1 + pv[nn + 1], g_qvh, g_qvl, idx);
                    } else if (part == 1) {
                        const size_t idx = ((size_t)bh * cT + tt) * cDK + dd;
                        split_store2(v0, v1, g_kh, g_kl, idx);
                    } else {
                        const size_t i0 = ((size_t)bh * cDK + dd) * cT + tt;
                        split_store(v0, g_vTh, g_vTl, i0);
                        split_store(v1, g_vTh, g_vTl, i0 + cT);
                    }
                } else if (MODE == 1) {
                    if (m < cS) {
                        const int hh = n >> 6, dd = n & 63;
                        split_store2(v0, v1, g_ph, g_pl,
                                     ((size_t)hh * 1024 + m) * cDK + dd);
                    }
                } else if (MODE == 2) {
                    const int s = n + m - (cT - 1);
                    float* dst = &g_bdg[((size_t)z * cT + m) * cT + s];
                    if ((unsigned)s < (unsigned)cT) dst[0] = v0;
                    if ((unsigned)(s + 1) < (unsigned)cT) dst[1] = v1;
                } else if (MODE == 3) {
                    const int bb = z >> 4;
                    const size_t o = ((size_t)z * cT + m) * cT + n;
                    const float2 bd = *(const float2*)&g_bdg[o];
                    const uint2  mk = *(const uint2*)&mask[((size_t)bb * cT + m) * cT + n];
                    float2 r;
                    r.x = mk.x ? (v0 + bd.x) * 0.125f : -100000.0f;
                    r.y = mk.y ? (v1 + bd.y) * 0.125f : -100000.0f;
                    *(float2*)&outf[o] = r;
                } else if (MODE == 4) {
                    const int bb = z >> 4, hh = z & 15;
                    const size_t idx = ((size_t)(bb * cT + m)) * cD + hh * cDK + n;
                    split_store2(v0, v1, g_cth, g_ctl, idx);
                } else {
                    float2 r = make_float2(v0 + bias[n], v1 + bias[n + 1]);
                    *(float2*)&outf[(size_t)m * cD + n] = r;
                }
            }
}

// ---------------------------------------------------------------------------
// Row softmax: fp32 in/out (wptr) + packed bf16 hi/lo weights for ctx GEMM.
// ---------------------------------------------------------------------------
__global__ __launch_bounds__(128)
void softmax_kernel(float* __restrict__ w)
{
    const size_t row = blockIdx.x;
    const int tid = threadIdx.x;
    float* p = w + row * cT + tid * 4;
    const float4 v = *(const float4*)p;

    float m = fmaxf(fmaxf(v.x, v.y), fmaxf(v.z, v.w));
#pragma unroll
    for (int o = 16; o; o >>= 1) m = fmaxf(m, __shfl_xor_sync(0xffffffffu, m, o));

    __shared__ float sm[4], ss[4];
    const int wi = tid >> 5, lane = tid & 31;
    if (lane == 0) sm[wi] = m;
    __syncthreads();
    m = fmaxf(fmaxf(sm[0], sm[1]), fmaxf(sm[2], sm[3]));

    const float e0 = __expf(v.x - m);
    const float e1 = __expf(v.y - m);
    const float e2 = __expf(v.z - m);
    const float e3 = __expf(v.w - m);
    float s = e0 + e1 + e2 + e3;
#pragma unroll
    for (int o = 16; o; o >>= 1) s += __shfl_xor_sync(0xffffffffu, s, o);
    if (lane == 0) ss[wi] = s;
    __syncthreads();
    s = ss[0] + ss[1] + ss[2] + ss[3];

    const float inv = 1.0f / s;
    const float w0 = e0 * inv, w1 = e1 * inv, w2 = e2 * inv, w3 = e3 * inv;
    *(float4*)p = make_float4(w0, w1, w2, w3);

    bf16 h0 = __float2bfloat16_rn(w0), h1 = __float2bfloat16_rn(w1);
    bf16 h2 = __float2bfloat16_rn(w2), h3 = __float2bfloat16_rn(w3);
    const size_t base = row * cT + tid * 4;
    *(uint2*)(g_wh + base) = make_uint2(pk2(h0, h1), pk2(h2, h3));
    *(uint2*)(g_wl + base) = make_uint2(
        pk2(__float2bfloat16_rn(w0 - __bfloat162float(h0)),
            __float2bfloat16_rn(w1 - __bfloat162float(h1))),
        pk2(__float2bfloat16_rn(w2 - __bfloat162float(h2)),
            __float2bfloat16_rn(w3 - __bfloat162float(h3))));
}

// ---------------------------------------------------------------------------
// kernel_launch
// ---------------------------------------------------------------------------
extern "C" void kernel_launch(void* const* d_in, const int* in_sizes, int n_in,
                              void* d_out, int out_size)
{
    const float*        x    = (const float*)d_in[0];
    const unsigned int* mask = (const unsigned int*)d_in[1];
    const float*        pos  = (const float*)d_in[2];
    const float*        Wqkv = (const float*)d_in[3];
    const float*        bqkv = (const float*)d_in[4];
    const float*        Wpos = (const float*)d_in[5];
    const float*        posu = (const float*)d_in[6];
    const float*        posv = (const float*)d_in[7];
    const float*        Wout = (const float*)d_in[8];
    const float*        bout = (const float*)d_in[9];
    float* out = (float*)d_out;

    const int nOut = cB * cT * cD;
    const int nW   = cBH * cT * cT;

    float* wptr;
    if (out_size >= nOut + nW) {
        wptr = out + nOut;
    } else {
        void* p = nullptr;
        cudaGetSymbolAddress(&p, g_w);
        wptr = (float*)p;
    }

    void *pxh, *pxl, *pWqh, *pWql, *pWph, *pWpl, *ppsh, *ppsl, *pWoh, *pWol;
    void *pquh, *pqul, *pqvh, *pqvl, *pkh, *pkl, *pvTh, *pvTl, *pph, *ppl;
    void *pwh, *pwl, *pcth, *pctl;
    cudaGetSymbolAddress(&pxh, g_xh);   cudaGetSymbolAddress(&pxl, g_xl);
    cudaGetSymbolAddress(&pWqh, g_Wqh); cudaGetSymbolAddress(&pWql, g_Wql);
    cudaGetSymbolAddress(&pWph, g_Wph); cudaGetSymbolAddress(&pWpl, g_Wpl);
    cudaGetSymbolAddress(&ppsh, g_psh); cudaGetSymbolAddress(&ppsl, g_psl);
    cudaGetSymbolAddress(&pWoh, g_Woh); cudaGetSymbolAddress(&pWol, g_Wol);
    cudaGetSymbolAddress(&pquh, g_quh); cudaGetSymbolAddress(&pqul, g_qul);
    cudaGetSymbolAddress(&pqvh, g_qvh); cudaGetSymbolAddress(&pqvl, g_qvl);
    cudaGetSymbolAddress(&pkh, g_kh);   cudaGetSymbolAddress(&pkl, g_kl);
    cudaGetSymbolAddress(&pvTh, g_vTh); cudaGetSymbolAddress(&pvTl, g_vTl);
    cudaGetSymbolAddress(&pph, g_ph);   cudaGetSymbolAddress(&ppl, g_pl);
    cudaGetSymbolAddress(&pwh, g_wh);   cudaGetSymbolAddress(&pwl, g_wl);
    cudaGetSymbolAddress(&pcth, g_cth); cudaGetSymbolAddress(&pctl, g_ctl);

    cudaFuncSetAttribute(bmma<0>, cudaFuncAttributeMaxDynamicSharedMemorySize, SMEM_B);
    cudaFuncSetAttribute(bmma<1>, cudaFuncAttributeMaxDynamicSharedMemorySize, SMEM_B);
    cudaFuncSetAttribute(bmma<2>, cudaFuncAttributeMaxDynamicSharedMemorySize, SMEM_B);
    cudaFuncSetAttribute(bmma<3>, cudaFuncAttributeMaxDynamicSharedMemorySize, SMEM_B);
    cudaFuncSetAttribute((bmma<4, 64>), cudaFuncAttributeMaxDynamicSharedMemorySize, SMEM_B);
    cudaFuncSetAttribute(bmma<5>, cudaFuncAttributeMaxDynamicSharedMemorySize, SMEM_B);

    // 0. Operand splits (pure bandwidth)
    conv_split<<<4096, 256>>>(x,    (bf16*)pxh,  (bf16*)pxl,  4096 * 1024, 4096 * 1024);
    conv_split<<<3072, 256>>>(Wqkv, (bf16*)pWqh, (bf16*)pWql, 3072 * 1024, 3072 * 1024);
    conv_split<<<1024, 256>>>(Wpos, (bf16*)pWph, (bf16*)pWpl, 1024 * 1024, 1024 * 1024);
    conv_split<<<1024, 256>>>(pos,  (bf16*)ppsh, (bf16*)ppsl, 1024 * 1024, cS * 1024);
    conv_split<<<1024, 256>>>(Wout, (bf16*)pWoh, (bf16*)pWol, 1024 * 1024, 1024 * 1024);

    // 1. QKV projection (+bias, +posu/posv) -> qu/qv/k/vT bf16 splits
    bmma<0><<<dim3(24, 32), 256, SMEM_B>>>((bf16*)pxh, (bf16*)pxl, (bf16*)pWqh, (bf16*)pWql,
                                           bqkv, posu, posv, nullptr, nullptr, 1024, 3072);

    // 2. Positional projection -> p bf16 splits
    bmma<1><<<dim3(8, 8), 256, SMEM_B>>>((bf16*)ppsh, (bf16*)ppsl, (bf16*)pWph, (bf16*)pWpl,
                                         nullptr, nullptr, nullptr, nullptr, nullptr, 1024, 1024);

    // 3. BD = qv @ p^T, window-skipped (5 of 8 n-tiles), pre-gathered store
    bmma<2><<<dim3(5, 4, cBH), 256, SMEM_B>>>((bf16*)pqvh, (bf16*)pqvl, (bf16*)pph, (bf16*)ppl,
                                              nullptr, nullptr, nullptr, nullptr, nullptr, 64, 1024);

    // 4. AC = qu @ k^T; scores = (AC + BD)*0.125 masked -> wptr
    bmma<3><<<dim3(4, 4, cBH), 256, SMEM_B>>>((bf16*)pquh, (bf16*)pqul, (bf16*)pkh, (bf16*)pkl,
                                              nullptr, nullptr, nullptr, mask, wptr, 64, 512);

    // 5. Softmax -> fp32 weights (output) + bf16 splits for ctx
    softmax_kernel<<<cBH * cT, 128>>>(wptr);

    // 6. ctx = w @ vT^T (narrow TN=64 tile) -> ctx bf16 splits
    bmma<4, 64><<<dim3(1, 4, cBH), 256, SMEM_B>>>((bf16*)pwh, (bf16*)pwl, (bf16*)pvTh, (bf16*)pvTl,
                                                  nullptr, nullptr, nullptr, nullptr, nullptr, 512, 64);

    // 7. out = ctx @ Wout^T + bout
    bmma<5><<<dim3(8, 32), 256, SMEM_B>>>((bf16*)pcth, (bf16*)pctl, (bf16*)pWoh, (bf16*)pWol,
                                          bout, nullptr, nullptr, nullptr, out, 1024, 1024);
}